// round 13
// baseline (speedup 1.0000x reference)
#include <cuda_runtime.h>
#include <cstdint>
#include <math.h>

#define BB 32
#define SS 196
#define TT 64
#define HH 1024
#define VV 32000
#define RR 4096
#define NBW 148   // total grid (128 recurrence + 20 workers)
#define NBR 128   // blocks participating in recurrence barriers
#define NTILES 4000u

// k_recur recurrence-path smem byte offsets
#define OFF_W    128
#define OFF_X    (128 + 32768)
#define OFF_GATE (128 + 65536)
#define OFF_P2S  (OFF_GATE + 4096)
// worker/pgemm smem: 3 stages x (16KB A + 16KB B) after 128B header
#define SMEM_WK  (128 + 3*32768)

// ---------------- scratch ----------------
__device__ float g_M2 [(size_t)BB*SS*HH];
__device__ float g_ET [(size_t)TT*RR*BB];
__device__ float g_Wf [(size_t)128*16*4096];
__device__ float g_xf [(size_t)24*4096];
__device__ float g_Af [(size_t)16*131072];
__device__ float g_Wo [(size_t)32000*1024];
__device__ float g_AM2[(size_t)49*131072];
__device__ float g_BM2[(size_t)8*131072];
__device__ float g_AE [(size_t)16*131072];
__device__ float g_BE [(size_t)32*131072];
__device__ float g_h [BB*HH];
__device__ float g_c [BB*HH];
__device__ float g_scores[BB*SS];
__device__ unsigned g_bar;
__device__ unsigned g_p2done;
__device__ unsigned g_tile;

// ---------------- helpers ----------------
__device__ __forceinline__ float f2tf32(float x) {
    uint32_t u; asm("cvt.rna.tf32.f32 %0, %1;" : "=r"(u) : "f"(x));
    return __uint_as_float(u);
}
__device__ __forceinline__ void mma_op(float* c, const uint32_t* a, const uint32_t* b) {
    asm volatile(
        "mma.sync.aligned.m16n8k8.row.col.f32.tf32.tf32.f32 "
        "{%0,%1,%2,%3},{%4,%5,%6,%7},{%8,%9},{%0,%1,%2,%3};"
        : "+f"(c[0]), "+f"(c[1]), "+f"(c[2]), "+f"(c[3])
        : "r"(a[0]), "r"(a[1]), "r"(a[2]), "r"(a[3]), "r"(b[0]), "r"(b[1]));
}
__device__ __forceinline__ uint32_t smem_u32(const void* p) {
    uint32_t a;
    asm("{ .reg .u64 t; cvta.to.shared.u64 t, %1; cvt.u32.u64 %0, t; }" : "=r"(a) : "l"(p));
    return a;
}
__device__ __forceinline__ size_t xf_off(int k, int n, int parity) {
    int cc = k >> 7;
    int ccp = (cc < 8) ? cc : (cc + parity * 8);
    int c8 = (k >> 3) & 15;
    int nt = n >> 3;
    int ln = ((n & 7) << 2) | (k & 3);
    int q  = (k >> 2) & 1;
    return ((size_t)(ccp * 16 + c8) * 4 + nt) * 64 + (size_t)ln * 2 + q;
}

#define MB_WAIT(mbar, par) do { uint32_t _d; \
    do { asm volatile("{\n\t.reg .pred p;\n\t" \
        "mbarrier.try_wait.parity.acquire.cta.shared::cta.b64 p, [%1], %2;\n\t" \
        "selp.b32 %0, 1, 0, p;\n\t}" \
        : "=r"(_d) : "r"(mbar), "r"((uint32_t)(par)) : "memory"); } while (!_d); } while (0)

#define BULK_CP(dst, src, mb) \
    asm volatile("cp.async.bulk.shared::cta.global.mbarrier::complete_tx::bytes " \
                 "[%0], [%1], %2, [%3];" \
                 :: "r"(dst), "l"(src), "r"(16384u), "r"(mb) : "memory")

// ---------------- worker tile: 128x128 logits tile, 1024 threads ----------------
__device__ __forceinline__ void worker_tile(
    char* smem, uint32_t sbase, int mblk, int nblk, uint32_t gs0,
    const float* __restrict__ bias, float* __restrict__ out)
{
    const int tid = threadIdx.x;
    const int warp = tid >> 5, lane = tid & 31;
    const int wm = warp >> 2, wn = warp & 3;
    const int grp = lane >> 2, tg = lane & 3;
    float acc[4][4] = {};

    auto issue = [&](int s) {
        int buf = (int)((gs0 + (uint32_t)s) % 3u);
        uint32_t mb = sbase + buf * 8;
        uint32_t ad = sbase + 128 + buf * 32768;
        uint32_t bd = ad + 16384;
        const float* as = g_Af + ((size_t)mblk * 128 + s * 4) * 1024;
        const float* bs = g_Wo + ((size_t)nblk * 128 + s * 4) * 1024;
        asm volatile("mbarrier.arrive.expect_tx.shared.b64 _, [%0], %1;"
                     :: "r"(mb), "r"(32768u) : "memory");
        BULK_CP(ad, as, mb);
        BULK_CP(bd, bs, mb);
    };

    if (tid == 0) { issue(0); issue(1); }

    for (int s = 0; s < 32; s++) {
        uint32_t g = gs0 + (uint32_t)s;
        int buf = (int)(g % 3u);
        MB_WAIT(sbase + buf * 8, (g / 3u) & 1u);
        const float4* Ab = (const float4*)(smem + 128 + buf * 32768);
        const float2* Bb = (const float2*)(smem + 128 + buf * 32768 + 16384);
        #pragma unroll
        for (int c8 = 0; c8 < 4; c8++) {
            float4 a0 = Ab[(c8 * 8 + wm) * 32 + lane];
            #pragma unroll
            for (int nt = 0; nt < 4; nt++) {
                float2 b2 = Bb[(c8 * 16 + wn * 4 + nt) * 32 + lane];
                mma_op(acc[nt], (const uint32_t*)&a0, (const uint32_t*)&b2);
            }
        }
        __syncthreads();
        if (tid == 0 && s + 2 < 32) issue(s + 2);
    }

    int m0 = mblk * 128 + wm * 16 + grp;
    int m2 = m0 + 8;
    #pragma unroll
    for (int nt = 0; nt < 4; nt++) {
        int ng = nblk * 128 + wn * 32 + nt * 8 + tg * 2;
        float b0 = __ldg(bias + ng), b1 = __ldg(bias + ng + 1);
        size_t r1 = ((size_t)(m0 & 31) * TT + (m0 >> 5)) * VV;
        size_t r2 = ((size_t)(m2 & 31) * TT + (m2 >> 5)) * VV;
        *(float2*)(out + r1 + ng) = make_float2(acc[nt][0] + b0, acc[nt][1] + b1);
        *(float2*)(out + r2 + ng) = make_float2(acc[nt][2] + b0, acc[nt][3] + b1);
    }
}

// ---------------- fragment packs (unchanged from R12) ----------------
__global__ __launch_bounds__(256) void k_packA(
    const float* __restrict__ src, const int* __restrict__ gidx,
    const float* __restrict__ gtab, float* __restrict__ dst)
{
    int idx = blockIdx.x * 256 + threadIdx.x;
    int lane = idx & 31, mtile = (idx >> 5) & 7, c8 = (idx >> 8) & 127, mblk = idx >> 15;
    int m0 = mblk * 128 + mtile * 16 + (lane >> 2);
    int k0 = c8 * 8 + (lane & 3);
    const float* r0 = gidx ? (gtab + (size_t)gidx[m0    ] * HH) : (src + (size_t)m0       * HH);
    const float* r1 = gidx ? (gtab + (size_t)gidx[m0 + 8] * HH) : (src + (size_t)(m0 + 8) * HH);
    float4 v;
    v.x = f2tf32(r0[k0]);     v.y = f2tf32(r1[k0]);
    v.z = f2tf32(r0[k0 + 4]); v.w = f2tf32(r1[k0 + 4]);
    ((float4*)dst)[idx] = v;
}

__global__ __launch_bounds__(256) void k_packB(
    const float* __restrict__ src, float* __restrict__ dst, int ldb, int trans)
{
    size_t idx = (size_t)blockIdx.x * 256 + threadIdx.x;
    int lane = (int)(idx & 31);
    int nt   = (int)((idx >> 5) & 15);
    int c8   = (int)((idx >> 9) & 127);
    int nblk = (int)(idx >> 16);
    int n = nblk * 128 + nt * 8 + (lane >> 2);
    int k = c8 * 8 + (lane & 3);
    float2 v;
    if (trans) {
        v.x = f2tf32(src[(size_t)k * ldb + n]);
        v.y = f2tf32(src[(size_t)(k + 4) * ldb + n]);
    } else {
        v.x = f2tf32(src[(size_t)n * ldb + k]);
        v.y = f2tf32(src[(size_t)n * ldb + k + 4]);
    }
    ((float2*)dst)[idx] = v;
}

__global__ __launch_bounds__(256) void k_packWF(
    const float* __restrict__ W_ih, const float* __restrict__ W_hh)
{
    int idx = blockIdx.x * 256 + threadIdx.x;
    int lane = idx & 31;
    int mt   = (idx >> 5) & 1;
    int c8   = (idx >> 6) & 15;
    int cc   = (idx >> 10) & 15;
    int blk  = idx >> 14;
    float4 v;
    float* o = (float*)&v;
    #pragma unroll
    for (int q = 0; q < 4; q++) {
        int m = mt * 16 + (lane >> 2) + 8 * (q & 1);
        int g = m >> 3, jo = m & 7;
        int r = g * 1024 + blk * 8 + jo;
        int k = (cc * 16 + c8) * 8 + (lane & 3) + 4 * (q >> 1);
        float wv = (k < 1024) ? W_ih[(size_t)r * 2048 + 1024 + k]
                              : W_hh[(size_t)r * 1024 + (k - 1024)];
        o[q] = f2tf32(wv);
    }
    ((float4*)g_Wf)[idx] = v;
}

// ---------------- no-CCTL global barrier (recurrence blocks only) ----------------
__device__ __forceinline__ void gridbar(unsigned target) {
    __syncthreads();
    if (threadIdx.x == 0) {
        unsigned one = 1u, x;
        asm volatile("red.release.gpu.global.add.u32 [%0], %1;"
                     :: "l"(&g_bar), "r"(one) : "memory");
        do {
            asm volatile("ld.acquire.gpu.global.u32 %0, [%1];"
                         : "=r"(x) : "l"(&g_bar));
        } while (x < target);
    }
    __syncthreads();
}

// ---------------- persistent recurrence + logits workers ----------------
__global__ __launch_bounds__(1024, 1) void k_recur(
    const float* __restrict__ memory,
    const float* __restrict__ b_ih, const float* __restrict__ b_hh,
    const float* __restrict__ b_out, float* __restrict__ out)
{
    extern __shared__ char smem[];
    const uint32_t sbase = smem_u32(smem);
    const int tid = threadIdx.x, bid = blockIdx.x;
    const int w = tid >> 5, lane = tid & 31;

    if (bid >= NBR) {
        // ================= logits worker block =================
        volatile unsigned* idxs = (volatile unsigned*)(smem + 64);
        if (tid == 0) {
            #pragma unroll
            for (int i = 0; i < 3; i++)
                asm volatile("mbarrier.init.shared.b64 [%0], %1;"
                             :: "r"(sbase + i * 8), "r"(1u) : "memory");
        }
        __syncthreads();
        uint32_t gs = 0;
        const unsigned BAR_END = 2u * TT * NBR;   // 16384
        while (true) {
            unsigned bar;
            asm volatile("ld.acquire.gpu.global.u32 %0, [%1];" : "=r"(bar) : "l"(&g_bar));
            if (bar >= BAR_END) break;            // recurrence done -> leave rest to k_ltail
            if (tid == 0) *idxs = atomicAdd(&g_tile, 1u);
            __syncthreads();
            unsigned idx = *idxs;
            __syncthreads();
            if (idx >= NTILES) break;
            int mblk = (int)(idx / 250u), nblk = (int)(idx % 250u);
            if (tid == 0) {
                unsigned want = 1024u * (unsigned)(mblk + 1), x;
                do {
                    asm volatile("ld.acquire.gpu.global.u32 %0, [%1];" : "=r"(x) : "l"(&g_bar));
                } while (x < want);
            }
            __syncthreads();
            worker_tile(smem, sbase, mblk, nblk, gs, b_out, out);
            gs += 32;
            __syncthreads();
        }
        return;
    }

    // ================= recurrence block (bid < 128) =================
    float* gate_s = (float*)(smem + OFF_GATE);
    float* p2s    = (float*)(smem + OFF_P2S);
    const uint32_t mb0 = sbase, mb1 = sbase + 8;
    const int sb = bid >> 2, sq = bid & 3;       // scores: batch sb, quarter sq

    if (tid == 0) {
        asm volatile("mbarrier.init.shared.b64 [%0], %1;" :: "r"(mb0), "r"(1u) : "memory");
        asm volatile("mbarrier.init.shared.b64 [%0], %1;" :: "r"(mb1), "r"(1u) : "memory");
    }
    __syncthreads();

    unsigned tgt = NBR;

    for (int t = 0; t < TT; t++) {
        const int par = t & 1;

        auto issue = [&](int cc, int slot) {
            uint32_t mb = (slot & 1) ? mb1 : mb0;
            uint32_t wd = sbase + OFF_W + (slot & 1) * 16384;
            uint32_t xd = sbase + OFF_X + (slot & 1) * 16384;
            const float* ws = g_Wf + ((size_t)bid * 16 + cc) * 4096;
            int ccp = (cc < 8) ? cc : (cc + par * 8);
            const float* xs = g_xf + (size_t)ccp * 4096;
            asm volatile("mbarrier.arrive.expect_tx.shared.b64 _, [%0], %1;"
                         :: "r"(mb), "r"(32768u) : "memory");
            BULK_CP(wd, ws, mb);
            BULK_CP(xd, xs, mb);
        };

        if (tid == 0) { issue(8, 0); issue(9, 1); }

        // ======== P1: scores for batch sb, rows sq*49..+48 ========
        for (int si = w; si < 49; si += 32) {
            int p = sb * SS + sq * 49 + si;
            const float4* m4 = (const float4*)(g_M2 + (size_t)p * HH);
            const float4* h4 = (const float4*)(g_h + sb * HH);
            float a = 0.f;
            #pragma unroll
            for (int i = 0; i < 8; i++) {
                float4 mv = m4[i * 32 + lane];
                float4 hv = __ldcg(&h4[i * 32 + lane]);
                a += mv.x*hv.x + mv.y*hv.y + mv.z*hv.z + mv.w*hv.w;
            }
            #pragma unroll
            for (int o = 16; o; o >>= 1) a += __shfl_xor_sync(0xffffffffu, a, o);
            if (!lane) g_scores[p] = a;
        }
        gridbar(tgt); tgt += NBR;

        // ======== P2: softmax + ctx -> x fragments ========
        {
            float* red  = p2s;
            float* swp  = p2s + 256;
            float* part = p2s + 512;
            int b = sb, jblk = sq;
            float v = -1e30f;
            if (tid < 256) {
                v = (tid < SS) ? __ldcg(&g_scores[b * SS + tid]) : -1e30f;
                red[tid] = v;
            }
            __syncthreads();
            for (int o = 128; o; o >>= 1) { if (tid < o) red[tid] = fmaxf(red[tid], red[tid+o]); __syncthreads(); }
            float mx = red[0]; __syncthreads();
            float e = 0.f;
            if (tid < 256) { e = (tid < SS) ? expf(v - mx) : 0.f; red[tid] = e; }
            __syncthreads();
            for (int o = 128; o; o >>= 1) { if (tid < o) red[tid] += red[tid+o]; __syncthreads(); }
            float inv = 1.f / red[0];
            if (tid < 256) swp[tid] = e * inv;
            __syncthreads();

            int jj = tid & 255, sp = tid >> 8;
            int j = jblk * 256 + jj;
            const float* mp = memory + ((size_t)b * SS + sp * 49) * HH + j;
            float acc2 = 0.f;
            #pragma unroll 7
            for (int s = 0; s < 49; s++)
                acc2 += swp[sp * 49 + s] * mp[(size_t)s * HH];
            part[sp * 256 + jj] = acc2;
            __syncthreads();
            if (tid < 256) {
                float cv = part[jj] + part[256+jj] + part[512+jj] + part[768+jj];
                g_xf[xf_off(j, b, 0)] = f2tf32(cv);
            }
            __syncthreads();
            if (tid == 0) {
                unsigned one = 1u;
                asm volatile("red.release.gpu.global.add.u32 [%0], %1;"
                             :: "l"(&g_p2done), "r"(one) : "memory");
            }
        }

        // ======== P3: gates pipeline (h-first) + cell ========
        {
            if (tid < 256) {
                const int w8 = tid >> 5;
                const int mt = w8 & 1, nt = w8 >> 1;
                const int grp = lane >> 2, tg = lane & 3;
                float acc[4] = {0.f, 0.f, 0.f, 0.f};

                #pragma unroll
                for (int i = 0; i < 16; i++) {
                    uint32_t mb = (i & 1) ? mb1 : mb0;
                    MB_WAIT(mb, (i >> 1) & 1);
                    const float4* wb = (const float4*)(smem + OFF_W + (i & 1) * 16384);
                    const float2* xb = (const float2*)(smem + OFF_X + (i & 1) * 16384);
                    #pragma unroll
                    for (int c8 = 0; c8 < 16; c8++) {
                        float4 a4 = wb[(c8 * 2 + mt) * 32 + lane];
                        float2 b2 = xb[(c8 * 4 + nt) * 32 + lane];
                        mma_op(acc, (const uint32_t*)&a4, (const uint32_t*)&b2);
                    }
                    asm volatile("bar.sync 7, 256;" ::: "memory");
                    if (tid == 0 && i < 14) {
                        int nxt = (i + 2 + 8) & 15;
                        if (i == 6) {
                            unsigned x, want = 128u * (unsigned)(t + 1);
                            do {
                                asm volatile("ld.acquire.gpu.global.u32 %0, [%1];"
                                             : "=r"(x) : "l"(&g_p2done));
                            } while (x < want);
                        }
                        issue(nxt, i + 2);
                    }
                }

                *(float2*)&gate_s[(mt*16 + grp    ) * 32 + nt*8 + tg*2] = make_float2(acc[0], acc[1]);
                *(float2*)&gate_s[(mt*16 + grp + 8) * 32 + nt*8 + tg*2] = make_float2(acc[2], acc[3]);
            }
            __syncthreads();
            if (tid < 256) {
                int b = tid & 31, jo = tid >> 5;
                int j = bid * 8 + jo;
                float pre[4];
                #pragma unroll
                for (int g = 0; g < 4; g++) {
                    pre[g] = gate_s[(g*8 + jo) * 32 + b]
                           + __ldg(&g_ET[((size_t)t * RR + g*1024 + j) * 32 + b])
                           + __ldg(&b_ih[g*1024 + j]) + __ldg(&b_hh[g*1024 + j]);
                }
                float ig = 1.f / (1.f + expf(-pre[0]));
                float fg = 1.f / (1.f + expf(-pre[1]));
                float gg = tanhf(pre[2]);
                float og = 1.f / (1.f + expf(-pre[3]));
                int idx = b * HH + j;
                float cn = fg * g_c[idx] + ig * gg;
                float hn = og * tanhf(cn);
                g_c[idx] = cn;
                g_h[idx] = hn;
                g_xf[xf_off(1024 + j, b, (t + 1) & 1)] = f2tf32(hn);
                int m = t * 32 + b;
                int mblk = m >> 7, mtile = (m >> 4) & 7;
                int q = ((m >> 3) & 1) + 2 * ((j >> 2) & 1);
                int lnA = ((m & 7) << 2) | (j & 3);
                g_Af[((((size_t)mblk * 128 + (j >> 3)) * 8 + mtile) * 32 + lnA) * 4 + q]
                    = f2tf32(hn);
            }
        }
        gridbar(tgt); tgt += NBR;
    }
}

// ---------------- logits tail: drain remaining tiles ----------------
__global__ __launch_bounds__(1024, 1) void k_ltail(
    const float* __restrict__ bias, float* __restrict__ out)
{
    extern __shared__ char smem[];
    const uint32_t sbase = smem_u32(smem);
    volatile unsigned* idxs = (volatile unsigned*)(smem + 64);
    if (threadIdx.x == 0) {
        #pragma unroll
        for (int i = 0; i < 3; i++)
            asm volatile("mbarrier.init.shared.b64 [%0], %1;"
                         :: "r"(sbase + i * 8), "r"(1u) : "memory");
    }
    __syncthreads();
    uint32_t gs = 0;
    while (true) {
        if (threadIdx.x == 0) *idxs = atomicAdd(&g_tile, 1u);
        __syncthreads();
        unsigned idx = *idxs;
        __syncthreads();
        if (idx >= NTILES) break;
        worker_tile(smem, sbase, (int)(idx / 250u), (int)(idx % 250u), gs, bias, out);
        gs += 32;
        __syncthreads();
    }
}

// ---------------- generalized pipelined GEMM (prologue M2 / E) ----------------
__global__ __launch_bounds__(256, 2) void k_pgemm(
    const float* __restrict__ Afrag, const float* __restrict__ Bfrag,
    float* __restrict__ C, int Nn, int mode)
{
    extern __shared__ char smem[];
    const uint32_t sbase = smem_u32(smem);
    const int tid = threadIdx.x;
    const int mblk = blockIdx.x, nblk = blockIdx.y;
    const int warp = tid >> 5, lane = tid & 31;
    const int wm = warp >> 1, wn = warp & 1;
    const int grp = lane >> 2, tg = lane & 3;

    if (tid == 0) {
        #pragma unroll
        for (int i = 0; i < 3; i++)
            asm volatile("mbarrier.init.shared.b64 [%0], %1;"
                         :: "r"(sbase + i * 8), "r"(1u) : "memory");
    }
    __syncthreads();

    float acc[2][8][4] = {};

    auto issue = [&](int s) {
        int buf = s % 3;
        uint32_t mb = sbase + buf * 8;
        uint32_t ad = sbase + 128 + buf * 32768;
        uint32_t bd = ad + 16384;
        const float* as = Afrag + ((size_t)mblk * 128 + s * 4) * 1024;
        const float* bs = Bfrag + ((size_t)nblk * 128 + s * 4) * 1024;
        asm volatile("mbarrier.arrive.expect_tx.shared.b64 _, [%0], %1;"
                     :: "r"(mb), "r"(32768u) : "memory");
        BULK_CP(ad, as, mb);
        BULK_CP(bd, bs, mb);
    };

    if (tid == 0) { issue(0); issue(1); }

    for (int s = 0; s < 32; s++) {
        int buf = s % 3;
        MB_WAIT(sbase + buf * 8, (s / 3) & 1);
        const float4* Ab = (const float4*)(smem + 128 + buf * 32768);
        const float2* Bb = (const float2*)(smem + 128 + buf * 32768 + 16384);
        #pragma unroll
        for (int c8 = 0; c8 < 4; c8++) {
            float4 a0 = Ab[(c8 * 8 + wm * 2 + 0) * 32 + lane];
            float4 a1 = Ab[(c8 * 8 + wm * 2 + 1) * 32 + lane];
            #pragma unroll
            for (int nt = 0; nt < 8; nt++) {
                float2 b2 = Bb[(c8 * 16 + wn * 8 + nt) * 32 + lane];
                mma_op(acc[0][nt], (const uint32_t*)&a0, (const uint32_t*)&b2);
                mma_op(acc[1][nt], (const uint32_t*)&a1, (const uint32_t*)&b2);
            }
        }
        __syncthreads();
        if (tid == 0 && s + 2 < 32) issue(s + 2);
    }

    #pragma unroll
    for (int mt = 0; mt < 2; mt++) {
        int m0 = mblk * 128 + (wm * 2 + mt) * 16 + grp;
        int m2 = m0 + 8;
        #pragma unroll
        for (int nt = 0; nt < 8; nt++) {
            int ng = nblk * 128 + wn * 64 + nt * 8 + tg * 2;
            float* a4 = acc[mt][nt];
            if (mode == 2) {
                int b1i = m0 >> 6, t1 = m0 & 63;
                int b2i = m2 >> 6, t2 = m2 & 63;
                size_t p1 = ((size_t)t1 * RR + ng) * 32 + b1i;
                size_t p2 = ((size_t)t2 * RR + ng) * 32 + b2i;
                C[p1] = a4[0]; C[p1 + 32] = a4[1];
                C[p2] = a4[2]; C[p2 + 32] = a4[3];
            } else {
                *(float2*)(C + (size_t)m0 * Nn + ng) = make_float2(a4[0], a4[1]);
                *(float2*)(C + (size_t)m2 * Nn + ng) = make_float2(a4[2], a4[3]);
            }
        }
    }
}

// ---------------- small kernels ----------------
__global__ void k_zero() {
    int i = blockIdx.x * 1024 + threadIdx.x;
    g_h[i] = 0.f; g_c[i] = 0.f;
    g_xf[i] = 0.f; g_xf[i + 32768] = 0.f; g_xf[i + 65536] = 0.f;
    if (i == 0) { g_bar = 0u; g_p2done = 0u; g_tile = 0u; }
}

__global__ void k_copy_hc(float* __restrict__ out) {
    int i = blockIdx.x * 512 + threadIdx.x;
    const size_t OFF = (size_t)BB * TT * VV;
    out[OFF + i] = g_h[i];
    out[OFF + (size_t)BB*HH + i] = g_c[i];
}

// ---------------- launch ----------------
extern "C" void kernel_launch(void* const* d_in, const int* in_sizes, int n_in,
                              void* d_out, int out_size)
{
    const float* memory  = (const float*)d_in[0];
    const int*   captions= (const int*  )d_in[1];
    const float* emb     = (const float*)d_in[2];
    const float* attn_W  = (const float*)d_in[3];
    const float* W_ih    = (const float*)d_in[4];
    const float* W_hh    = (const float*)d_in[5];
    const float* b_ih    = (const float*)d_in[6];
    const float* b_hh    = (const float*)d_in[7];
    const float* W_out   = (const float*)d_in[8];
    const float* b_out   = (const float*)d_in[9];
    float* out = (float*)d_out;

    static float *pM2 = nullptr, *pET = nullptr, *pWo = nullptr,
                 *pAM2 = nullptr, *pBM2 = nullptr, *pAE = nullptr, *pBE = nullptr;
    if (!pM2) {
        cudaGetSymbolAddress((void**)&pM2,  g_M2);
        cudaGetSymbolAddress((void**)&pET,  g_ET);
        cudaGetSymbolAddress((void**)&pWo,  g_Wo);
        cudaGetSymbolAddress((void**)&pAM2, g_AM2);
        cudaGetSymbolAddress((void**)&pBM2, g_BM2);
        cudaGetSymbolAddress((void**)&pAE,  g_AE);
        cudaGetSymbolAddress((void**)&pBE,  g_BE);
        cudaFuncSetAttribute(k_recur, cudaFuncAttributeMaxDynamicSharedMemorySize, SMEM_WK);
        cudaFuncSetAttribute(k_ltail, cudaFuncAttributeMaxDynamicSharedMemorySize, SMEM_WK);
        cudaFuncSetAttribute(k_pgemm, cudaFuncAttributeMaxDynamicSharedMemorySize, SMEM_WK);
    }

    k_zero<<<32, 1024>>>();

    // fragment packs
    k_packA<<<6272, 256>>>(memory, nullptr, nullptr, pAM2);
    k_packB<<<2048, 256>>>(attn_W, pBM2, HH, 1);
    k_packA<<<2048, 256>>>(nullptr, captions, emb, pAE);
    k_packB<<<8192, 256>>>(W_ih, pBE, 2048, 0);
    k_packWF<<<8192, 256>>>(W_ih, W_hh);
    k_packB<<<64000, 256>>>(W_out, pWo, HH, 0);

    // prologue GEMMs
    k_pgemm<<<dim3(49, 8), 256, SMEM_WK>>>(pAM2, pBM2, pM2, HH, 0);
    k_pgemm<<<dim3(16, 32), 256, SMEM_WK>>>(pAE, pBE, pET, RR, 2);

    // recurrence + overlapped logits workers
    k_recur<<<NBW, 1024, SMEM_WK>>>(memory, b_ih, b_hh, b_out, out);

    // drain remaining logits tiles
    k_ltail<<<NBW, 1024, SMEM_WK>>>(b_out, out);

    k_copy_hc<<<64, 512>>>(out);
}

// round 14
// speedup vs baseline: 1.1185x; 1.1185x over previous
#include <cuda_runtime.h>
#include <cstdint>
#include <math.h>

#define BB 32
#define SS 196
#define TT 64
#define HH 1024
#define VV 32000
#define RR 4096
#define NB 148

// k_recur smem byte offsets
#define OFF_W    128
#define OFF_X    (128 + 32768)
#define OFF_GATE (128 + 65536)
#define OFF_P2S  (OFF_GATE + 4096)
#define SMEM_RECUR (OFF_P2S + 6144)

// pgemm smem: 3 stages x (16KB A + 16KB B), mbarriers at base
#define SMEM_WK (128 + 3*32768)

// ---------------- scratch ----------------
__device__ float g_M2 [(size_t)BB*SS*HH];
__device__ float g_ET [(size_t)TT*RR*BB];
__device__ float g_Wf [(size_t)128*16*4096];
__device__ float g_xf [(size_t)24*4096];
__device__ float g_Af [(size_t)16*131072];
__device__ float g_Wo [(size_t)32000*1024];
__device__ float g_AM2[(size_t)49*131072];
__device__ float g_BM2[(size_t)8*131072];
__device__ float g_AE [(size_t)16*131072];
__device__ float g_BE [(size_t)32*131072];
__device__ float g_h [BB*HH];
__device__ float g_c [BB*HH];
__device__ float g_scores[BB*SS];
__device__ unsigned g_bar;
__device__ unsigned g_p2done;

// ---------------- helpers ----------------
__device__ __forceinline__ float f2tf32(float x) {
    uint32_t u; asm("cvt.rna.tf32.f32 %0, %1;" : "=r"(u) : "f"(x));
    return __uint_as_float(u);
}
__device__ __forceinline__ void mma_op(float* c, const uint32_t* a, const uint32_t* b) {
    asm volatile(
        "mma.sync.aligned.m16n8k8.row.col.f32.tf32.tf32.f32 "
        "{%0,%1,%2,%3},{%4,%5,%6,%7},{%8,%9},{%0,%1,%2,%3};"
        : "+f"(c[0]), "+f"(c[1]), "+f"(c[2]), "+f"(c[3])
        : "r"(a[0]), "r"(a[1]), "r"(a[2]), "r"(a[3]), "r"(b[0]), "r"(b[1]));
}
__device__ __forceinline__ uint32_t smem_u32(const void* p) {
    uint32_t a;
    asm("{ .reg .u64 t; cvta.to.shared.u64 t, %1; cvt.u32.u64 %0, t; }" : "=r"(a) : "l"(p));
    return a;
}
__device__ __forceinline__ size_t xf_off(int k, int n, int parity) {
    int cc = k >> 7;
    int ccp = (cc < 8) ? cc : (cc + parity * 8);
    int c8 = (k >> 3) & 15;
    int nt = n >> 3;
    int ln = ((n & 7) << 2) | (k & 3);
    int q  = (k >> 2) & 1;
    return ((size_t)(ccp * 16 + c8) * 4 + nt) * 64 + (size_t)ln * 2 + q;
}

#define MB_WAIT(mbar, par) do { uint32_t _d; \
    do { asm volatile("{\n\t.reg .pred p;\n\t" \
        "mbarrier.try_wait.parity.acquire.cta.shared::cta.b64 p, [%1], %2;\n\t" \
        "selp.b32 %0, 1, 0, p;\n\t}" \
        : "=r"(_d) : "r"(mbar), "r"((uint32_t)(par)) : "memory"); } while (!_d); } while (0)

#define BULK_CP(dst, src, mb) \
    asm volatile("cp.async.bulk.shared::cta.global.mbarrier::complete_tx::bytes " \
                 "[%0], [%1], %2, [%3];" \
                 :: "r"(dst), "l"(src), "r"(16384u), "r"(mb) : "memory")

// ---------------- pack bodies (verbatim formulas, rebased block index) ----------------
__device__ __forceinline__ void packA_body(
    int bi, const float* __restrict__ src, const int* __restrict__ gidx,
    const float* __restrict__ gtab, float* __restrict__ dst)
{
    int idx = bi * 256 + threadIdx.x;
    int lane = idx & 31, mtile = (idx >> 5) & 7, c8 = (idx >> 8) & 127, mblk = idx >> 15;
    int m0 = mblk * 128 + mtile * 16 + (lane >> 2);
    int k0 = c8 * 8 + (lane & 3);
    const float* r0 = gidx ? (gtab + (size_t)gidx[m0    ] * HH) : (src + (size_t)m0       * HH);
    const float* r1 = gidx ? (gtab + (size_t)gidx[m0 + 8] * HH) : (src + (size_t)(m0 + 8) * HH);
    float4 v;
    v.x = f2tf32(r0[k0]);     v.y = f2tf32(r1[k0]);
    v.z = f2tf32(r0[k0 + 4]); v.w = f2tf32(r1[k0 + 4]);
    ((float4*)dst)[idx] = v;
}

__device__ __forceinline__ void packB_body(
    int bi, const float* __restrict__ src, float* __restrict__ dst, int ldb, int trans)
{
    size_t idx = (size_t)bi * 256 + threadIdx.x;
    int lane = (int)(idx & 31);
    int nt   = (int)((idx >> 5) & 15);
    int c8   = (int)((idx >> 9) & 127);
    int nblk = (int)(idx >> 16);
    int n = nblk * 128 + nt * 8 + (lane >> 2);
    int k = c8 * 8 + (lane & 3);
    float2 v;
    if (trans) {
        v.x = f2tf32(src[(size_t)k * ldb + n]);
        v.y = f2tf32(src[(size_t)(k + 4) * ldb + n]);
    } else {
        v.x = f2tf32(src[(size_t)n * ldb + k]);
        v.y = f2tf32(src[(size_t)n * ldb + k + 4]);
    }
    ((float2*)dst)[idx] = v;
}

__device__ __forceinline__ void packWF_body(
    int bi, const float* __restrict__ W_ih, const float* __restrict__ W_hh)
{
    int idx = bi * 256 + threadIdx.x;
    int lane = idx & 31;
    int mt   = (idx >> 5) & 1;
    int c8   = (idx >> 6) & 15;
    int cc   = (idx >> 10) & 15;
    int blk  = idx >> 14;
    float4 v;
    float* o = (float*)&v;
    #pragma unroll
    for (int q = 0; q < 4; q++) {
        int m = mt * 16 + (lane >> 2) + 8 * (q & 1);
        int g = m >> 3, jo = m & 7;
        int r = g * 1024 + blk * 8 + jo;
        int k = (cc * 16 + c8) * 8 + (lane & 3) + 4 * (q >> 1);
        float wv = (k < 1024) ? W_ih[(size_t)r * 2048 + 1024 + k]
                              : W_hh[(size_t)r * 1024 + (k - 1024)];
        o[q] = f2tf32(wv);
    }
    ((float4*)g_Wf)[idx] = v;
}

// ---------------- fused prep: all packs + zero-init in ONE launch ----------------
// blocks: [0,64000) Wo | [64000,72192) WF | [72192,80384) BE | [80384,82432) BM2
//         [82432,88704) AM2 | [88704,90752) AE | [90752,90880) zero
__global__ __launch_bounds__(256) void k_prep(
    const float* __restrict__ memory, const int* __restrict__ captions,
    const float* __restrict__ emb, const float* __restrict__ attn_W,
    const float* __restrict__ W_ih, const float* __restrict__ W_hh,
    const float* __restrict__ W_out)
{
    int b = blockIdx.x;
    if      (b < 64000) packB_body(b,          W_out,  g_Wo,  HH,   0);
    else if (b < 72192) packWF_body(b - 64000, W_ih,   W_hh);
    else if (b < 80384) packB_body(b - 72192,  W_ih,   g_BE,  2048, 0);
    else if (b < 82432) packB_body(b - 80384,  attn_W, g_BM2, HH,   1);
    else if (b < 88704) packA_body(b - 82432,  memory, nullptr, nullptr, g_AM2);
    else if (b < 90752) packA_body(b - 88704,  nullptr, captions, emb,   g_AE);
    else {
        int i = (b - 90752) * 256 + threadIdx.x;     // 0..32767
        g_h[i] = 0.f; g_c[i] = 0.f;
        g_xf[i] = 0.f; g_xf[i + 32768] = 0.f; g_xf[i + 65536] = 0.f;
        if (i == 0) { g_bar = 0u; g_p2done = 0u; }
    }
}

// ---------------- no-CCTL global barrier ----------------
__device__ __forceinline__ void gridbar(unsigned target) {
    __syncthreads();
    if (threadIdx.x == 0) {
        unsigned one = 1u, x;
        asm volatile("red.release.gpu.global.add.u32 [%0], %1;"
                     :: "l"(&g_bar), "r"(one) : "memory");
        do {
            asm volatile("ld.acquire.gpu.global.u32 %0, [%1];"
                         : "=r"(x) : "l"(&g_bar));
        } while (x < target);
    }
    __syncthreads();
}

// ---------------- persistent recurrence (byte-identical logic to R12) ----------------
__global__ __launch_bounds__(1024, 1) void k_recur(
    const float* __restrict__ memory,
    const float* __restrict__ b_ih, const float* __restrict__ b_hh)
{
    extern __shared__ char smem[];
    float* gate_s = (float*)(smem + OFF_GATE);
    float* p2s    = (float*)(smem + OFF_P2S);
    const uint32_t sbase = smem_u32(smem);
    const uint32_t mb0 = sbase, mb1 = sbase + 8;

    const int tid = threadIdx.x, bid = blockIdx.x;
    const int w = tid >> 5, lane = tid & 31;
    const bool gateblk = (bid < 128);

    if (tid == 0) {
        asm volatile("mbarrier.init.shared.b64 [%0], %1;" :: "r"(mb0), "r"(1u) : "memory");
        asm volatile("mbarrier.init.shared.b64 [%0], %1;" :: "r"(mb1), "r"(1u) : "memory");
    }
    __syncthreads();

    unsigned tgt = NB;

    for (int t = 0; t < TT; t++) {
        const int par = t & 1;

        auto issue = [&](int cc, int slot) {
            uint32_t mb = (slot & 1) ? mb1 : mb0;
            uint32_t wd = sbase + OFF_W + (slot & 1) * 16384;
            uint32_t xd = sbase + OFF_X + (slot & 1) * 16384;
            const float* ws = g_Wf + ((size_t)bid * 16 + cc) * 4096;
            int ccp = (cc < 8) ? cc : (cc + par * 8);
            const float* xs = g_xf + (size_t)ccp * 4096;
            asm volatile("mbarrier.arrive.expect_tx.shared.b64 _, [%0], %1;"
                         :: "r"(mb), "r"(32768u) : "memory");
            BULK_CP(wd, ws, mb);
            BULK_CP(xd, xs, mb);
        };

        if (gateblk && tid == 0) { issue(8, 0); issue(9, 1); }

        // ======== P1: scores ========
        for (int p = bid * 32 + w; p < BB * SS; p += NB * 32) {
            int b = p / SS;
            const float4* m4 = (const float4*)(g_M2 + (size_t)p * HH);
            const float4* h4 = (const float4*)(g_h + b * HH);
            float a = 0.f;
            #pragma unroll
            for (int i = 0; i < 8; i++) {
                float4 mv = m4[i * 32 + lane];
                float4 hv = __ldcg(&h4[i * 32 + lane]);
                a += mv.x*hv.x + mv.y*hv.y + mv.z*hv.z + mv.w*hv.w;
            }
            #pragma unroll
            for (int o = 16; o; o >>= 1) a += __shfl_xor_sync(0xffffffffu, a, o);
            if (!lane) g_scores[p] = a;
        }
        gridbar(tgt); tgt += NB;

        // ======== P2: softmax + ctx -> x fragments ========
        if (gateblk) {
            float* red  = p2s;
            float* swp  = p2s + 256;
            float* part = p2s + 512;
            int b = bid >> 2, jblk = bid & 3;
            float v = -1e30f;
            if (tid < 256) {
                v = (tid < SS) ? __ldcg(&g_scores[b * SS + tid]) : -1e30f;
                red[tid] = v;
            }
            __syncthreads();
            for (int o = 128; o; o >>= 1) { if (tid < o) red[tid] = fmaxf(red[tid], red[tid+o]); __syncthreads(); }
            float mx = red[0]; __syncthreads();
            float e = 0.f;
            if (tid < 256) { e = (tid < SS) ? expf(v - mx) : 0.f; red[tid] = e; }
            __syncthreads();
            for (int o = 128; o; o >>= 1) { if (tid < o) red[tid] += red[tid+o]; __syncthreads(); }
            float inv = 1.f / red[0];
            if (tid < 256) swp[tid] = e * inv;
            __syncthreads();

            int jj = tid & 255, sp = tid >> 8;
            int j = jblk * 256 + jj;
            const float* mp = memory + ((size_t)b * SS + sp * 49) * HH + j;
            float acc2 = 0.f;
            #pragma unroll 7
            for (int s = 0; s < 49; s++)
                acc2 += swp[sp * 49 + s] * mp[(size_t)s * HH];
            part[sp * 256 + jj] = acc2;
            __syncthreads();
            if (tid < 256) {
                float cv = part[jj] + part[256+jj] + part[512+jj] + part[768+jj];
                g_xf[xf_off(j, b, 0)] = f2tf32(cv);
            }
            __syncthreads();
            if (tid == 0) {
                unsigned one = 1u;
                asm volatile("red.release.gpu.global.add.u32 [%0], %1;"
                             :: "l"(&g_p2done), "r"(one) : "memory");
            }
        }

        // ======== P3: gates pipeline (h-first) + cell ========
        if (gateblk) {
            if (tid < 256) {
                const int w8 = tid >> 5;
                const int mt = w8 & 1, nt = w8 >> 1;
                const int grp = lane >> 2, tg = lane & 3;
                float acc[4] = {0.f, 0.f, 0.f, 0.f};

                #pragma unroll
                for (int i = 0; i < 16; i++) {
                    uint32_t mb = (i & 1) ? mb1 : mb0;
                    MB_WAIT(mb, (i >> 1) & 1);
                    const float4* wb = (const float4*)(smem + OFF_W + (i & 1) * 16384);
                    const float2* xb = (const float2*)(smem + OFF_X + (i & 1) * 16384);
                    #pragma unroll
                    for (int c8 = 0; c8 < 16; c8++) {
                        float4 a4 = wb[(c8 * 2 + mt) * 32 + lane];
                        float2 b2 = xb[(c8 * 4 + nt) * 32 + lane];
                        mma_op(acc, (const uint32_t*)&a4, (const uint32_t*)&b2);
                    }
                    asm volatile("bar.sync 7, 256;" ::: "memory");
                    if (tid == 0 && i < 14) {
                        int nxt = (i + 2 + 8) & 15;
                        if (i == 6) {
                            unsigned x, want = 128u * (unsigned)(t + 1);
                            do {
                                asm volatile("ld.acquire.gpu.global.u32 %0, [%1];"
                                             : "=r"(x) : "l"(&g_p2done));
                            } while (x < want);
                        }
                        issue(nxt, i + 2);
                    }
                }

                *(float2*)&gate_s[(mt*16 + grp    ) * 32 + nt*8 + tg*2] = make_float2(acc[0], acc[1]);
                *(float2*)&gate_s[(mt*16 + grp + 8) * 32 + nt*8 + tg*2] = make_float2(acc[2], acc[3]);
            }
            __syncthreads();
            if (tid < 256) {
                int b = tid & 31, jo = tid >> 5;
                int j = bid * 8 + jo;
                float pre[4];
                #pragma unroll
                for (int g = 0; g < 4; g++) {
                    pre[g] = gate_s[(g*8 + jo) * 32 + b]
                           + __ldg(&g_ET[((size_t)t * RR + g*1024 + j) * 32 + b])
                           + __ldg(&b_ih[g*1024 + j]) + __ldg(&b_hh[g*1024 + j]);
                }
                float ig = 1.f / (1.f + expf(-pre[0]));
                float fg = 1.f / (1.f + expf(-pre[1]));
                float gg = tanhf(pre[2]);
                float og = 1.f / (1.f + expf(-pre[3]));
                int idx = b * HH + j;
                float cn = fg * g_c[idx] + ig * gg;
                float hn = og * tanhf(cn);
                g_c[idx] = cn;
                g_h[idx] = hn;
                g_xf[xf_off(1024 + j, b, (t + 1) & 1)] = f2tf32(hn);
                int m = t * 32 + b;
                int mblk = m >> 7, mtile = (m >> 4) & 7;
                int q = ((m >> 3) & 1) + 2 * ((j >> 2) & 1);
                int lnA = ((m & 7) << 2) | (j & 3);
                g_Af[((((size_t)mblk * 128 + (j >> 3)) * 8 + mtile) * 32 + lnA) * 4 + q]
                    = f2tf32(hn);
            }
        }
        gridbar(tgt); tgt += NB;
    }
}

// ---------------- pipelined GEMM body (proven; modes 0/1/2) ----------------
__device__ __forceinline__ void pgemm_body(
    char* smem, uint32_t sbase,
    const float* __restrict__ Afrag, const float* __restrict__ Bfrag,
    float* __restrict__ C, int Nn, int mode, const float* __restrict__ bias,
    int mblk, int nblk)
{
    const int tid = threadIdx.x;
    const int warp = tid >> 5, lane = tid & 31;
    const int wm = warp >> 1, wn = warp & 1;
    const int grp = lane >> 2, tg = lane & 3;

    if (tid == 0) {
        #pragma unroll
        for (int i = 0; i < 3; i++)
            asm volatile("mbarrier.init.shared.b64 [%0], %1;"
                         :: "r"(sbase + i * 8), "r"(1u) : "memory");
    }
    __syncthreads();

    float acc[2][8][4] = {};

    auto issue = [&](int s) {
        int buf = s % 3;
        uint32_t mb = sbase + buf * 8;
        uint32_t ad = sbase + 128 + buf * 32768;
        uint32_t bd = ad + 16384;
        const float* as = Afrag + ((size_t)mblk * 128 + s * 4) * 1024;
        const float* bs = Bfrag + ((size_t)nblk * 128 + s * 4) * 1024;
        asm volatile("mbarrier.arrive.expect_tx.shared.b64 _, [%0], %1;"
                     :: "r"(mb), "r"(32768u) : "memory");
        BULK_CP(ad, as, mb);
        BULK_CP(bd, bs, mb);
    };

    if (tid == 0) { issue(0); issue(1); }

    for (int s = 0; s < 32; s++) {
        int buf = s % 3;
        MB_WAIT(sbase + buf * 8, (s / 3) & 1);
        const float4* Ab = (const float4*)(smem + 128 + buf * 32768);
        const float2* Bb = (const float2*)(smem + 128 + buf * 32768 + 16384);
        #pragma unroll
        for (int c8 = 0; c8 < 4; c8++) {
            float4 a0 = Ab[(c8 * 8 + wm * 2 + 0) * 32 + lane];
            float4 a1 = Ab[(c8 * 8 + wm * 2 + 1) * 32 + lane];
            #pragma unroll
            for (int nt = 0; nt < 8; nt++) {
                float2 b2 = Bb[(c8 * 16 + wn * 8 + nt) * 32 + lane];
                mma_op(acc[0][nt], (const uint32_t*)&a0, (const uint32_t*)&b2);
                mma_op(acc[1][nt], (const uint32_t*)&a1, (const uint32_t*)&b2);
            }
        }
        __syncthreads();
        if (tid == 0 && s + 2 < 32) issue(s + 2);
    }

    #pragma unroll
    for (int mt = 0; mt < 2; mt++) {
        int m0 = mblk * 128 + (wm * 2 + mt) * 16 + grp;
        int m2 = m0 + 8;
        #pragma unroll
        for (int nt = 0; nt < 8; nt++) {
            int ng = nblk * 128 + wn * 64 + nt * 8 + tg * 2;
            float* a4 = acc[mt][nt];
            if (mode == 1) {
                float b0 = __ldg(bias + ng), b1 = __ldg(bias + ng + 1);
                size_t r1 = ((size_t)(m0 & 31) * TT + (m0 >> 5)) * Nn;
                size_t r2 = ((size_t)(m2 & 31) * TT + (m2 >> 5)) * Nn;
                *(float2*)(C + r1 + ng) = make_float2(a4[0] + b0, a4[1] + b1);
                *(float2*)(C + r2 + ng) = make_float2(a4[2] + b0, a4[3] + b1);
            } else if (mode == 2) {
                int b1i = m0 >> 6, t1 = m0 & 63;
                int b2i = m2 >> 6, t2 = m2 & 63;
                size_t p1 = ((size_t)t1 * RR + ng) * 32 + b1i;
                size_t p2 = ((size_t)t2 * RR + ng) * 32 + b2i;
                C[p1] = a4[0]; C[p1 + 32] = a4[1];
                C[p2] = a4[2]; C[p2 + 32] = a4[3];
            } else {
                *(float2*)(C + (size_t)m0 * Nn + ng) = make_float2(a4[0], a4[1]);
                *(float2*)(C + (size_t)m2 * Nn + ng) = make_float2(a4[2], a4[3]);
            }
        }
    }
}

// fused prologue GEMMs: blocks [0,392) = M2 (49x8), [392,904) = E (16x32)
__global__ __launch_bounds__(256, 2) void k_pgemm2()
{
    extern __shared__ char smem[];
    const uint32_t sbase = smem_u32(smem);
    int b = blockIdx.x;
    if (b < 392)
        pgemm_body(smem, sbase, g_AM2, g_BM2, g_M2, HH, 0, nullptr, b % 49, b / 49);
    else {
        b -= 392;
        pgemm_body(smem, sbase, g_AE, g_BE, g_ET, RR, 2, nullptr, b % 16, b / 16);
    }
}

// logits GEMM (grid 16 x 250)
__global__ __launch_bounds__(256, 2) void k_logits(
    const float* __restrict__ bias, float* __restrict__ out)
{
    extern __shared__ char smem[];
    const uint32_t sbase = smem_u32(smem);
    pgemm_body(smem, sbase, g_Af, g_Wo, out, VV, 1, bias, blockIdx.x, blockIdx.y);
}

// ---------------- epilogue ----------------
__global__ void k_copy_hc(float* __restrict__ out) {
    int i = blockIdx.x * 512 + threadIdx.x;
    const size_t OFF = (size_t)BB * TT * VV;
    out[OFF + i] = g_h[i];
    out[OFF + (size_t)BB*HH + i] = g_c[i];
}

// ---------------- launch ----------------
extern "C" void kernel_launch(void* const* d_in, const int* in_sizes, int n_in,
                              void* d_out, int out_size)
{
    const float* memory  = (const float*)d_in[0];
    const int*   captions= (const int*  )d_in[1];
    const float* emb     = (const float*)d_in[2];
    const float* attn_W  = (const float*)d_in[3];
    const float* W_ih    = (const float*)d_in[4];
    const float* W_hh    = (const float*)d_in[5];
    const float* b_ih    = (const float*)d_in[6];
    const float* b_hh    = (const float*)d_in[7];
    const float* W_out   = (const float*)d_in[8];
    const float* b_out   = (const float*)d_in[9];
    float* out = (float*)d_out;

    static bool init = false;
    if (!init) {
        init = true;
        cudaFuncSetAttribute(k_recur,  cudaFuncAttributeMaxDynamicSharedMemorySize, SMEM_RECUR);
        cudaFuncSetAttribute(k_pgemm2, cudaFuncAttributeMaxDynamicSharedMemorySize, SMEM_WK);
        cudaFuncSetAttribute(k_logits, cudaFuncAttributeMaxDynamicSharedMemorySize, SMEM_WK);
    }

    // all packs + zero in one launch
    k_prep<<<90880, 256>>>(memory, captions, emb, attn_W, W_ih, W_hh, W_out);

    // prologue GEMMs (M2 + E) in one launch
    k_pgemm2<<<904, 256, SMEM_WK>>>();

    // recurrence
    k_recur<<<NB, 1024, SMEM_RECUR>>>(memory, b_ih, b_hh);

    // logits
    k_logits<<<dim3(16, 250), 256, SMEM_WK>>>(b_out, out);

    k_copy_hc<<<64, 512>>>(out);
}

// round 15
// speedup vs baseline: 1.2246x; 1.0949x over previous
#include <cuda_runtime.h>
#include <cuda_fp16.h>
#include <cstdint>
#include <math.h>

#define BB 32
#define SS 196
#define TT 64
#define HH 1024
#define VV 32000
#define RR 4096
#define NB 148

// k_recur smem byte offsets
#define OFF_W    128
#define OFF_X    (128 + 32768)
#define OFF_GATE (128 + 65536)
#define OFF_P2S  (OFF_GATE + 4096)
#define SMEM_RECUR (OFF_P2S + 6144)

// tf32 pgemm smem (M2/E): 3 stages x (16KB+16KB)
#define SMEM_WK (128 + 3*32768)
// f16 logits smem: 3 stages x (8KB A + 8KB B)
#define SMEM_LF (128 + 3*16384)

// ---------------- scratch ----------------
__device__ float  g_M2 [(size_t)BB*SS*HH];
__device__ float  g_ET [(size_t)TT*RR*BB];
__device__ float  g_Wf [(size_t)128*16*4096];
__device__ float  g_xf [(size_t)24*4096];
__device__ __half g_Af [(size_t)16*131072];    // logits A f16 fragments (written by recur)
__device__ __half g_Wo [(size_t)32000*1024];   // logits B f16 fragments
__device__ float  g_AM2[(size_t)49*131072];
__device__ float  g_BM2[(size_t)8*131072];
__device__ float  g_AE [(size_t)16*131072];
__device__ float  g_BE [(size_t)32*131072];
__device__ float  g_h [BB*HH];
__device__ float  g_c [BB*HH];
__device__ float  g_scores[BB*SS];
__device__ unsigned g_bar;
__device__ unsigned g_p2done;

// ---------------- helpers ----------------
__device__ __forceinline__ float f2tf32(float x) {
    uint32_t u; asm("cvt.rna.tf32.f32 %0, %1;" : "=r"(u) : "f"(x));
    return __uint_as_float(u);
}
__device__ __forceinline__ void mma_op(float* c, const uint32_t* a, const uint32_t* b) {
    asm volatile(
        "mma.sync.aligned.m16n8k8.row.col.f32.tf32.tf32.f32 "
        "{%0,%1,%2,%3},{%4,%5,%6,%7},{%8,%9},{%0,%1,%2,%3};"
        : "+f"(c[0]), "+f"(c[1]), "+f"(c[2]), "+f"(c[3])
        : "r"(a[0]), "r"(a[1]), "r"(a[2]), "r"(a[3]), "r"(b[0]), "r"(b[1]));
}
__device__ __forceinline__ void mma_f16(float* c, const uint4& a, const uint2& b) {
    asm volatile(
        "mma.sync.aligned.m16n8k16.row.col.f32.f16.f16.f32 "
        "{%0,%1,%2,%3},{%4,%5,%6,%7},{%8,%9},{%0,%1,%2,%3};"
        : "+f"(c[0]), "+f"(c[1]), "+f"(c[2]), "+f"(c[3])
        : "r"(a.x), "r"(a.y), "r"(a.z), "r"(a.w), "r"(b.x), "r"(b.y));
}
__device__ __forceinline__ uint32_t smem_u32(const void* p) {
    uint32_t a;
    asm("{ .reg .u64 t; cvta.to.shared.u64 t, %1; cvt.u32.u64 %0, t; }" : "=r"(a) : "l"(p));
    return a;
}
__device__ __forceinline__ size_t xf_off(int k, int n, int parity) {
    int cc = k >> 7;
    int ccp = (cc < 8) ? cc : (cc + parity * 8);
    int c8 = (k >> 3) & 15;
    int nt = n >> 3;
    int ln = ((n & 7) << 2) | (k & 3);
    int q  = (k >> 2) & 1;
    return ((size_t)(ccp * 16 + c8) * 4 + nt) * 64 + (size_t)ln * 2 + q;
}

#define MB_WAIT(mbar, par) do { uint32_t _d; \
    do { asm volatile("{\n\t.reg .pred p;\n\t" \
        "mbarrier.try_wait.parity.acquire.cta.shared::cta.b64 p, [%1], %2;\n\t" \
        "selp.b32 %0, 1, 0, p;\n\t}" \
        : "=r"(_d) : "r"(mbar), "r"((uint32_t)(par)) : "memory"); } while (!_d); } while (0)

#define BULK_CPN(dst, src, bytes, mb) \
    asm volatile("cp.async.bulk.shared::cta.global.mbarrier::complete_tx::bytes " \
                 "[%0], [%1], %2, [%3];" \
                 :: "r"(dst), "l"(src), "r"((uint32_t)(bytes)), "r"(mb) : "memory")

// ---------------- fragment packs (tf32, unchanged from R12) ----------------
__global__ __launch_bounds__(256) void k_packA(
    const float* __restrict__ src, const int* __restrict__ gidx,
    const float* __restrict__ gtab, float* __restrict__ dst)
{
    int idx = blockIdx.x * 256 + threadIdx.x;
    int lane = idx & 31, mtile = (idx >> 5) & 7, c8 = (idx >> 8) & 127, mblk = idx >> 15;
    int m0 = mblk * 128 + mtile * 16 + (lane >> 2);
    int k0 = c8 * 8 + (lane & 3);
    const float* r0 = gidx ? (gtab + (size_t)gidx[m0    ] * HH) : (src + (size_t)m0       * HH);
    const float* r1 = gidx ? (gtab + (size_t)gidx[m0 + 8] * HH) : (src + (size_t)(m0 + 8) * HH);
    float4 v;
    v.x = f2tf32(r0[k0]);     v.y = f2tf32(r1[k0]);
    v.z = f2tf32(r0[k0 + 4]); v.w = f2tf32(r1[k0 + 4]);
    ((float4*)dst)[idx] = v;
}

__global__ __launch_bounds__(256) void k_packB(
    const float* __restrict__ src, float* __restrict__ dst, int ldb, int trans)
{
    size_t idx = (size_t)blockIdx.x * 256 + threadIdx.x;
    int lane = (int)(idx & 31);
    int nt   = (int)((idx >> 5) & 15);
    int c8   = (int)((idx >> 9) & 127);
    int nblk = (int)(idx >> 16);
    int n = nblk * 128 + nt * 8 + (lane >> 2);
    int k = c8 * 8 + (lane & 3);
    float2 v;
    if (trans) {
        v.x = f2tf32(src[(size_t)k * ldb + n]);
        v.y = f2tf32(src[(size_t)(k + 4) * ldb + n]);
    } else {
        v.x = f2tf32(src[(size_t)n * ldb + k]);
        v.y = f2tf32(src[(size_t)n * ldb + k + 4]);
    }
    ((float2*)dst)[idx] = v;
}

__global__ __launch_bounds__(256) void k_packWF(
    const float* __restrict__ W_ih, const float* __restrict__ W_hh)
{
    int idx = blockIdx.x * 256 + threadIdx.x;
    int lane = idx & 31;
    int mt   = (idx >> 5) & 1;
    int c8   = (idx >> 6) & 15;
    int cc   = (idx >> 10) & 15;
    int blk  = idx >> 14;
    float4 v;
    float* o = (float*)&v;
    #pragma unroll
    for (int q = 0; q < 4; q++) {
        int m = mt * 16 + (lane >> 2) + 8 * (q & 1);
        int g = m >> 3, jo = m & 7;
        int r = g * 1024 + blk * 8 + jo;
        int k = (cc * 16 + c8) * 8 + (lane & 3) + 4 * (q >> 1);
        float wv = (k < 1024) ? W_ih[(size_t)r * 2048 + 1024 + k]
                              : W_hh[(size_t)r * 1024 + (k - 1024)];
        o[q] = f2tf32(wv);
    }
    ((float4*)g_Wf)[idx] = v;
}

// ---------------- W_out f16 B-fragment pack (m16n8k16) ----------------
// idx -> one uint2 (b0,b1 = halves k0,k0+1,k0+8,k0+9 at column n)
// half layout: (((nblk*64 + c16)*16 + ntile)*32 + lane)*4 + j
__global__ __launch_bounds__(256) void k_packWoH(const float* __restrict__ W_out)
{
    size_t idx = (size_t)blockIdx.x * 256 + threadIdx.x;   // 0 .. 8191999
    int lane  = (int)(idx & 31);
    int ntile = (int)((idx >> 5) & 15);
    int c16   = (int)((idx >> 9) & 63);
    int nblk  = (int)(idx >> 15);
    int grp = lane >> 2, tg = lane & 3;
    int n = nblk * 128 + ntile * 8 + grp;
    int k = c16 * 16 + tg * 2;
    const float* src = W_out + (size_t)n * HH + k;
    __half2 lo = __floats2half2_rn(src[0], src[1]);
    __half2 hi = __floats2half2_rn(src[8], src[9]);
    ((__half2*)g_Wo)[idx * 2]     = lo;
    ((__half2*)g_Wo)[idx * 2 + 1] = hi;
}

// ---------------- no-CCTL global barrier ----------------
__device__ __forceinline__ void gridbar(unsigned target) {
    __syncthreads();
    if (threadIdx.x == 0) {
        unsigned one = 1u, x;
        asm volatile("red.release.gpu.global.add.u32 [%0], %1;"
                     :: "l"(&g_bar), "r"(one) : "memory");
        do {
            asm volatile("ld.acquire.gpu.global.u32 %0, [%1];"
                         : "=r"(x) : "l"(&g_bar));
        } while (x < target);
    }
    __syncthreads();
}

// ---------------- persistent recurrence (R12, only the Af store changed) ----------------
__global__ __launch_bounds__(1024, 1) void k_recur(
    const float* __restrict__ memory,
    const float* __restrict__ b_ih, const float* __restrict__ b_hh)
{
    extern __shared__ char smem[];
    float* gate_s = (float*)(smem + OFF_GATE);
    float* p2s    = (float*)(smem + OFF_P2S);
    const uint32_t sbase = smem_u32(smem);
    const uint32_t mb0 = sbase, mb1 = sbase + 8;

    const int tid = threadIdx.x, bid = blockIdx.x;
    const int w = tid >> 5, lane = tid & 31;
    const bool gateblk = (bid < 128);

    if (tid == 0) {
        asm volatile("mbarrier.init.shared.b64 [%0], %1;" :: "r"(mb0), "r"(1u) : "memory");
        asm volatile("mbarrier.init.shared.b64 [%0], %1;" :: "r"(mb1), "r"(1u) : "memory");
    }
    __syncthreads();

    unsigned tgt = NB;

    for (int t = 0; t < TT; t++) {
        const int par = t & 1;

        auto issue = [&](int cc, int slot) {
            uint32_t mb = (slot & 1) ? mb1 : mb0;
            uint32_t wd = sbase + OFF_W + (slot & 1) * 16384;
            uint32_t xd = sbase + OFF_X + (slot & 1) * 16384;
            const float* ws = g_Wf + ((size_t)bid * 16 + cc) * 4096;
            int ccp = (cc < 8) ? cc : (cc + par * 8);
            const float* xs = g_xf + (size_t)ccp * 4096;
            asm volatile("mbarrier.arrive.expect_tx.shared.b64 _, [%0], %1;"
                         :: "r"(mb), "r"(32768u) : "memory");
            BULK_CPN(wd, ws, 16384u, mb);
            BULK_CPN(xd, xs, 16384u, mb);
        };

        if (gateblk && tid == 0) { issue(8, 0); issue(9, 1); }

        // ======== P1: scores ========
        for (int p = bid * 32 + w; p < BB * SS; p += NB * 32) {
            int b = p / SS;
            const float4* m4 = (const float4*)(g_M2 + (size_t)p * HH);
            const float4* h4 = (const float4*)(g_h + b * HH);
            float a = 0.f;
            #pragma unroll
            for (int i = 0; i < 8; i++) {
                float4 mv = m4[i * 32 + lane];
                float4 hv = __ldcg(&h4[i * 32 + lane]);
                a += mv.x*hv.x + mv.y*hv.y + mv.z*hv.z + mv.w*hv.w;
            }
            #pragma unroll
            for (int o = 16; o; o >>= 1) a += __shfl_xor_sync(0xffffffffu, a, o);
            if (!lane) g_scores[p] = a;
        }
        gridbar(tgt); tgt += NB;

        // ======== P2: softmax + ctx -> x fragments ========
        if (gateblk) {
            float* red  = p2s;
            float* swp  = p2s + 256;
            float* part = p2s + 512;
            int b = bid >> 2, jblk = bid & 3;
            float v = -1e30f;
            if (tid < 256) {
                v = (tid < SS) ? __ldcg(&g_scores[b * SS + tid]) : -1e30f;
                red[tid] = v;
            }
            __syncthreads();
            for (int o = 128; o; o >>= 1) { if (tid < o) red[tid] = fmaxf(red[tid], red[tid+o]); __syncthreads(); }
            float mx = red[0]; __syncthreads();
            float e = 0.f;
            if (tid < 256) { e = (tid < SS) ? expf(v - mx) : 0.f; red[tid] = e; }
            __syncthreads();
            for (int o = 128; o; o >>= 1) { if (tid < o) red[tid] += red[tid+o]; __syncthreads(); }
            float inv = 1.f / red[0];
            if (tid < 256) swp[tid] = e * inv;
            __syncthreads();

            int jj = tid & 255, sp = tid >> 8;
            int j = jblk * 256 + jj;
            const float* mp = memory + ((size_t)b * SS + sp * 49) * HH + j;
            float acc2 = 0.f;
            #pragma unroll 7
            for (int s = 0; s < 49; s++)
                acc2 += swp[sp * 49 + s] * mp[(size_t)s * HH];
            part[sp * 256 + jj] = acc2;
            __syncthreads();
            if (tid < 256) {
                float cv = part[jj] + part[256+jj] + part[512+jj] + part[768+jj];
                g_xf[xf_off(j, b, 0)] = f2tf32(cv);
            }
            __syncthreads();
            if (tid == 0) {
                unsigned one = 1u;
                asm volatile("red.release.gpu.global.add.u32 [%0], %1;"
                             :: "l"(&g_p2done), "r"(one) : "memory");
            }
        }

        // ======== P3: gates pipeline (h-first) + cell ========
        if (gateblk) {
            if (tid < 256) {
                const int w8 = tid >> 5;
                const int mt = w8 & 1, nt = w8 >> 1;
                const int grp = lane >> 2, tg = lane & 3;
                float acc[4] = {0.f, 0.f, 0.f, 0.f};

                #pragma unroll
                for (int i = 0; i < 16; i++) {
                    uint32_t mb = (i & 1) ? mb1 : mb0;
                    MB_WAIT(mb, (i >> 1) & 1);
                    const float4* wb = (const float4*)(smem + OFF_W + (i & 1) * 16384);
                    const float2* xb = (const float2*)(smem + OFF_X + (i & 1) * 16384);
                    #pragma unroll
                    for (int c8 = 0; c8 < 16; c8++) {
                        float4 a4 = wb[(c8 * 2 + mt) * 32 + lane];
                        float2 b2 = xb[(c8 * 4 + nt) * 32 + lane];
                        mma_op(acc, (const uint32_t*)&a4, (const uint32_t*)&b2);
                    }
                    asm volatile("bar.sync 7, 256;" ::: "memory");
                    if (tid == 0 && i < 14) {
                        int nxt = (i + 2 + 8) & 15;
                        if (i == 6) {
                            unsigned x, want = 128u * (unsigned)(t + 1);
                            do {
                                asm volatile("ld.acquire.gpu.global.u32 %0, [%1];"
                                             : "=r"(x) : "l"(&g_p2done));
                            } while (x < want);
                        }
                        issue(nxt, i + 2);
                    }
                }

                *(float2*)&gate_s[(mt*16 + grp    ) * 32 + nt*8 + tg*2] = make_float2(acc[0], acc[1]);
                *(float2*)&gate_s[(mt*16 + grp + 8) * 32 + nt*8 + tg*2] = make_float2(acc[2], acc[3]);
            }
            __syncthreads();
            if (tid < 256) {
                int b = tid & 31, jo = tid >> 5;
                int j = bid * 8 + jo;
                float pre[4];
                #pragma unroll
                for (int g = 0; g < 4; g++) {
                    pre[g] = gate_s[(g*8 + jo) * 32 + b]
                           + __ldg(&g_ET[((size_t)t * RR + g*1024 + j) * 32 + b])
                           + __ldg(&b_ih[g*1024 + j]) + __ldg(&b_hh[g*1024 + j]);
                }
                float ig = 1.f / (1.f + expf(-pre[0]));
                float fg = 1.f / (1.f + expf(-pre[1]));
                float gg = tanhf(pre[2]);
                float og = 1.f / (1.f + expf(-pre[3]));
                int idx = b * HH + j;
                float cn = fg * g_c[idx] + ig * gg;
                float hn = og * tanhf(cn);
                g_c[idx] = cn;
                g_h[idx] = hn;
                g_xf[xf_off(1024 + j, b, (t + 1) & 1)] = f2tf32(hn);
                // f16 A-fragment store for logits (m16n8k16 layout)
                int m = t * 32 + b;
                int mblk = m >> 7, c16 = j >> 4, mtile = (m >> 4) & 7;
                int q   = ((m >> 3) & 1) + 2 * ((j >> 3) & 1);
                int lnA = ((m & 7) << 2) | ((j >> 1) & 3);
                size_t off = (((((size_t)mblk * 64 + c16) * 8 + mtile) * 32 + lnA) * 8)
                           + (size_t)(q * 2 + (j & 1));
                g_Af[off] = __float2half_rn(hn);
            }
        }
        gridbar(tgt); tgt += NB;
    }
}

// ---------------- f16 pipelined logits GEMM ----------------
__global__ __launch_bounds__(256, 2) void k_logits(
    const float* __restrict__ bias, float* __restrict__ out)
{
    extern __shared__ char smem[];
    const uint32_t sbase = smem_u32(smem);
    const int tid = threadIdx.x;
    const int mblk = blockIdx.x, nblk = blockIdx.y;
    const int warp = tid >> 5, lane = tid & 31;
    const int wm = warp >> 1, wn = warp & 1;
    const int grp = lane >> 2, tg = lane & 3;

    if (tid == 0) {
        #pragma unroll
        for (int i = 0; i < 3; i++)
            asm volatile("mbarrier.init.shared.b64 [%0], %1;"
                         :: "r"(sbase + i * 8), "r"(1u) : "memory");
    }
    __syncthreads();

    float acc[2][8][4] = {};

    auto issue = [&](int s) {
        int buf = s % 3;
        uint32_t mb = sbase + buf * 8;
        uint32_t ad = sbase + 128 + buf * 16384;
        uint32_t bd = ad + 8192;
        const __half* as = g_Af + ((size_t)mblk * 64 + s * 2) * 2048;
        const __half* bs = g_Wo + ((size_t)nblk * 64 + s * 2) * 2048;
        asm volatile("mbarrier.arrive.expect_tx.shared.b64 _, [%0], %1;"
                     :: "r"(mb), "r"(16384u) : "memory");
        BULK_CPN(ad, as, 8192u, mb);
        BULK_CPN(bd, bs, 8192u, mb);
    };

    if (tid == 0) { issue(0); issue(1); }

    for (int s = 0; s < 32; s++) {
        int buf = s % 3;
        MB_WAIT(sbase + buf * 8, (s / 3) & 1);
        const uint4* Ab = (const uint4*)(smem + 128 + buf * 16384);
        const uint2* Bb = (const uint2*)(smem + 128 + buf * 16384 + 8192);
        #pragma unroll
        for (int cl = 0; cl < 2; cl++) {
            uint4 a0 = Ab[(cl * 8 + wm * 2 + 0) * 32 + lane];
            uint4 a1 = Ab[(cl * 8 + wm * 2 + 1) * 32 + lane];
            #pragma unroll
            for (int nt = 0; nt < 8; nt++) {
                uint2 b2 = Bb[(cl * 16 + wn * 8 + nt) * 32 + lane];
                mma_f16(acc[0][nt], a0, b2);
                mma_f16(acc[1][nt], a1, b2);
            }
        }
        __syncthreads();
        if (tid == 0 && s + 2 < 32) issue(s + 2);
    }

    #pragma unroll
    for (int mt = 0; mt < 2; mt++) {
        int m0 = mblk * 128 + (wm * 2 + mt) * 16 + grp;
        int m2 = m0 + 8;
        #pragma unroll
        for (int nt = 0; nt < 8; nt++) {
            int ng = nblk * 128 + wn * 64 + nt * 8 + tg * 2;
            float* a4 = acc[mt][nt];
            float b0 = __ldg(bias + ng), b1 = __ldg(bias + ng + 1);
            size_t r1 = ((size_t)(m0 & 31) * TT + (m0 >> 5)) * VV;
            size_t r2 = ((size_t)(m2 & 31) * TT + (m2 >> 5)) * VV;
            *(float2*)(out + r1 + ng) = make_float2(a4[0] + b0, a4[1] + b1);
            *(float2*)(out + r2 + ng) = make_float2(a4[2] + b0, a4[3] + b1);
        }
    }
}

// ---------------- tf32 pipelined GEMM (prologue M2 / E; unchanged from R12) ----------------
__global__ __launch_bounds__(256, 2) void k_pgemm(
    const float* __restrict__ Afrag, const float* __restrict__ Bfrag,
    float* __restrict__ C, int Nn, int mode)
{
    extern __shared__ char smem[];
    const uint32_t sbase = smem_u32(smem);
    const int tid = threadIdx.x;
    const int mblk = blockIdx.x, nblk = blockIdx.y;
    const int warp = tid >> 5, lane = tid & 31;
    const int wm = warp >> 1, wn = warp & 1;
    const int grp = lane >> 2, tg = lane & 3;

    if (tid == 0) {
        #pragma unroll
        for (int i = 0; i < 3; i++)
            asm volatile("mbarrier.init.shared.b64 [%0], %1;"
                         :: "r"(sbase + i * 8), "r"(1u) : "memory");
    }
    __syncthreads();

    float acc[2][8][4] = {};

    auto issue = [&](int s) {
        int buf = s % 3;
        uint32_t mb = sbase + buf * 8;
        uint32_t ad = sbase + 128 + buf * 32768;
        uint32_t bd = ad + 16384;
        const float* as = Afrag + ((size_t)mblk * 128 + s * 4) * 1024;
        const float* bs = Bfrag + ((size_t)nblk * 128 + s * 4) * 1024;
        asm volatile("mbarrier.arrive.expect_tx.shared.b64 _, [%0], %1;"
                     :: "r"(mb), "r"(32768u) : "memory");
        BULK_CPN(ad, as, 16384u, mb);
        BULK_CPN(bd, bs, 16384u, mb);
    };

    if (tid == 0) { issue(0); issue(1); }

    for (int s = 0; s < 32; s++) {
        int buf = s % 3;
        MB_WAIT(sbase + buf * 8, (s / 3) & 1);
        const float4* Ab = (const float4*)(smem + 128 + buf * 32768);
        const float2* Bb = (const float2*)(smem + 128 + buf * 32768 + 16384);
        #pragma unroll
        for (int c8 = 0; c8 < 4; c8++) {
            float4 a0 = Ab[(c8 * 8 + wm * 2 + 0) * 32 + lane];
            float4 a1 = Ab[(c8 * 8 + wm * 2 + 1) * 32 + lane];
            #pragma unroll
            for (int nt = 0; nt < 8; nt++) {
                float2 b2 = Bb[(c8 * 16 + wn * 8 + nt) * 32 + lane];
                mma_op(acc[0][nt], (const uint32_t*)&a0, (const uint32_t*)&b2);
                mma_op(acc[1][nt], (const uint32_t*)&a1, (const uint32_t*)&b2);
            }
        }
        __syncthreads();
        if (tid == 0 && s + 2 < 32) issue(s + 2);
    }

    #pragma unroll
    for (int mt = 0; mt < 2; mt++) {
        int m0 = mblk * 128 + (wm * 2 + mt) * 16 + grp;
        int m2 = m0 + 8;
        #pragma unroll
        for (int nt = 0; nt < 8; nt++) {
            int ng = nblk * 128 + wn * 64 + nt * 8 + tg * 2;
            float* a4 = acc[mt][nt];
            if (mode == 2) {
                int b1i = m0 >> 6, t1 = m0 & 63;
                int b2i = m2 >> 6, t2 = m2 & 63;
                size_t p1 = ((size_t)t1 * RR + ng) * 32 + b1i;
                size_t p2 = ((size_t)t2 * RR + ng) * 32 + b2i;
                C[p1] = a4[0]; C[p1 + 32] = a4[1];
                C[p2] = a4[2]; C[p2 + 32] = a4[3];
            } else {
                *(float2*)(C + (size_t)m0 * Nn + ng) = make_float2(a4[0], a4[1]);
                *(float2*)(C + (size_t)m2 * Nn + ng) = make_float2(a4[2], a4[3]);
            }
        }
    }
}

// ---------------- small kernels ----------------
__global__ void k_zero() {
    int i = blockIdx.x * 1024 + threadIdx.x;
    g_h[i] = 0.f; g_c[i] = 0.f;
    g_xf[i] = 0.f; g_xf[i + 32768] = 0.f; g_xf[i + 65536] = 0.f;
    if (i == 0) { g_bar = 0u; g_p2done = 0u; }
}

__global__ void k_copy_hc(float* __restrict__ out) {
    int i = blockIdx.x * 512 + threadIdx.x;
    const size_t OFF = (size_t)BB * TT * VV;
    out[OFF + i] = g_h[i];
    out[OFF + (size_t)BB*HH + i] = g_c[i];
}

// ---------------- launch ----------------
extern "C" void kernel_launch(void* const* d_in, const int* in_sizes, int n_in,
                              void* d_out, int out_size)
{
    const float* memory  = (const float*)d_in[0];
    const int*   captions= (const int*  )d_in[1];
    const float* emb     = (const float*)d_in[2];
    const float* attn_W  = (const float*)d_in[3];
    const float* W_ih    = (const float*)d_in[4];
    const float* W_hh    = (const float*)d_in[5];
    const float* b_ih    = (const float*)d_in[6];
    const float* b_hh    = (const float*)d_in[7];
    const float* W_out   = (const float*)d_in[8];
    const float* b_out   = (const float*)d_in[9];
    float* out = (float*)d_out;

    static float *pM2 = nullptr, *pET = nullptr,
                 *pAM2 = nullptr, *pBM2 = nullptr, *pAE = nullptr, *pBE = nullptr;
    if (!pM2) {
        cudaGetSymbolAddress((void**)&pM2,  g_M2);
        cudaGetSymbolAddress((void**)&pET,  g_ET);
        cudaGetSymbolAddress((void**)&pAM2, g_AM2);
        cudaGetSymbolAddress((void**)&pBM2, g_BM2);
        cudaGetSymbolAddress((void**)&pAE,  g_AE);
        cudaGetSymbolAddress((void**)&pBE,  g_BE);
        cudaFuncSetAttribute(k_recur,  cudaFuncAttributeMaxDynamicSharedMemorySize, SMEM_RECUR);
        cudaFuncSetAttribute(k_pgemm,  cudaFuncAttributeMaxDynamicSharedMemorySize, SMEM_WK);
        cudaFuncSetAttribute(k_logits, cudaFuncAttributeMaxDynamicSharedMemorySize, SMEM_LF);
    }

    k_zero<<<32, 1024>>>();

    // fragment packs
    k_packA<<<6272, 256>>>(memory, nullptr, nullptr, pAM2);
    k_packB<<<2048, 256>>>(attn_W, pBM2, HH, 1);
    k_packA<<<2048, 256>>>(nullptr, captions, emb, pAE);
    k_packB<<<8192, 256>>>(W_ih, pBE, 2048, 0);
    k_packWF<<<8192, 256>>>(W_ih, W_hh);
    k_packWoH<<<32000, 256>>>(W_out);

    // prologue GEMMs
    k_pgemm<<<dim3(49, 8), 256, SMEM_WK>>>(pAM2, pBM2, pM2, HH, 0);
    k_pgemm<<<dim3(16, 32), 256, SMEM_WK>>>(pAE, pBE, pET, RR, 2);

    // recurrence
    k_recur<<<NB, 1024, SMEM_RECUR>>>(memory, b_ih, b_hh);

    // f16 logits
    k_logits<<<dim3(16, 250), 256, SMEM_LF>>>(b_out, out);

    k_copy_hc<<<64, 512>>>(out);
}

// round 16
// speedup vs baseline: 1.5049x; 1.2289x over previous
#include <cuda_runtime.h>
#include <cuda_fp16.h>
#include <cstdint>
#include <math.h>

#define BB 32
#define SS 196
#define TT 64
#define HH 1024
#define VV 32000
#define RR 4096
#define NB 148

// k_recur smem byte offsets (f16 gate stages: 2 x 8KB per operand)
#define OFF_W    128
#define OFF_X    (128 + 16384)
#define OFF_GATE (128 + 32768)
#define OFF_P2S  (OFF_GATE + 4096)
#define SMEM_RECUR (OFF_P2S + 6144)

// tf32 pgemm smem (M2/E)
#define SMEM_WK (128 + 3*32768)
// f16 logits smem
#define SMEM_LF (128 + 3*16384)

// ---------------- scratch ----------------
__device__ float  g_M2 [(size_t)BB*SS*HH];
__device__ float  g_ET [(size_t)TT*RR*BB];
__device__ __half g_Wfh[(size_t)128*16*4096];  // f16 gate weight fragments (8KB/chunk)
__device__ __half g_xfh[(size_t)24*4096];      // f16 x fragments (ctx 0-7, h 8-23 parity)
__device__ __half g_Af [(size_t)16*131072];    // logits A f16 fragments
__device__ __half g_Wo [(size_t)32000*1024];   // logits B f16 fragments
__device__ float  g_AM2[(size_t)49*131072];
__device__ float  g_BM2[(size_t)8*131072];
__device__ float  g_AE [(size_t)16*131072];
__device__ float  g_BE [(size_t)32*131072];
__device__ float  g_h [BB*HH];
__device__ float  g_c [BB*HH];
__device__ float  g_scores[BB*SS];
__device__ unsigned g_bar;
__device__ unsigned g_p2done;

// ---------------- helpers ----------------
__device__ __forceinline__ float f2tf32(float x) {
    uint32_t u; asm("cvt.rna.tf32.f32 %0, %1;" : "=r"(u) : "f"(x));
    return __uint_as_float(u);
}
__device__ __forceinline__ void mma_op(float* c, const uint32_t* a, const uint32_t* b) {
    asm volatile(
        "mma.sync.aligned.m16n8k8.row.col.f32.tf32.tf32.f32 "
        "{%0,%1,%2,%3},{%4,%5,%6,%7},{%8,%9},{%0,%1,%2,%3};"
        : "+f"(c[0]), "+f"(c[1]), "+f"(c[2]), "+f"(c[3])
        : "r"(a[0]), "r"(a[1]), "r"(a[2]), "r"(a[3]), "r"(b[0]), "r"(b[1]));
}
__device__ __forceinline__ void mma_f16(float* c, const uint4& a, const uint2& b) {
    asm volatile(
        "mma.sync.aligned.m16n8k16.row.col.f32.f16.f16.f32 "
        "{%0,%1,%2,%3},{%4,%5,%6,%7},{%8,%9},{%0,%1,%2,%3};"
        : "+f"(c[0]), "+f"(c[1]), "+f"(c[2]), "+f"(c[3])
        : "r"(a.x), "r"(a.y), "r"(a.z), "r"(a.w), "r"(b.x), "r"(b.y));
}
__device__ __forceinline__ uint32_t smem_u32(const void* p) {
    uint32_t a;
    asm("{ .reg .u64 t; cvta.to.shared.u64 t, %1; cvt.u32.u64 %0, t; }" : "=r"(a) : "l"(p));
    return a;
}
// f16 B-fragment offset for x(k, n); chunks of K=128; m16n8k16 layout
__device__ __forceinline__ size_t xf_off_h(int k, int n, int parity) {
    int cc = k >> 7;
    int ccp = (cc < 8) ? cc : (cc + parity * 8);
    int c16 = (k >> 4) & 7;
    int nt = n >> 3;
    int kk = k & 15;
    int lane = ((n & 7) << 2) | ((kk >> 1) & 3);
    int hidx = ((kk >> 3) << 1) | (kk & 1);
    return ((((size_t)(ccp * 8 + c16) * 4 + nt) * 32 + lane) * 4) + hidx;
}

#define MB_WAIT(mbar, par) do { uint32_t _d; \
    do { asm volatile("{\n\t.reg .pred p;\n\t" \
        "mbarrier.try_wait.parity.acquire.cta.shared::cta.b64 p, [%1], %2;\n\t" \
        "selp.b32 %0, 1, 0, p;\n\t}" \
        : "=r"(_d) : "r"(mbar), "r"((uint32_t)(par)) : "memory"); } while (!_d); } while (0)

#define BULK_CPN(dst, src, bytes, mb) \
    asm volatile("cp.async.bulk.shared::cta.global.mbarrier::complete_tx::bytes " \
                 "[%0], [%1], %2, [%3];" \
                 :: "r"(dst), "l"(src), "r"((uint32_t)(bytes)), "r"(mb) : "memory")

// ---------------- tf32 fragment packs (prologue; unchanged) ----------------
__global__ __launch_bounds__(256) void k_packA(
    const float* __restrict__ src, const int* __restrict__ gidx,
    const float* __restrict__ gtab, float* __restrict__ dst)
{
    int idx = blockIdx.x * 256 + threadIdx.x;
    int lane = idx & 31, mtile = (idx >> 5) & 7, c8 = (idx >> 8) & 127, mblk = idx >> 15;
    int m0 = mblk * 128 + mtile * 16 + (lane >> 2);
    int k0 = c8 * 8 + (lane & 3);
    const float* r0 = gidx ? (gtab + (size_t)gidx[m0    ] * HH) : (src + (size_t)m0       * HH);
    const float* r1 = gidx ? (gtab + (size_t)gidx[m0 + 8] * HH) : (src + (size_t)(m0 + 8) * HH);
    float4 v;
    v.x = f2tf32(r0[k0]);     v.y = f2tf32(r1[k0]);
    v.z = f2tf32(r0[k0 + 4]); v.w = f2tf32(r1[k0 + 4]);
    ((float4*)dst)[idx] = v;
}

__global__ __launch_bounds__(256) void k_packB(
    const float* __restrict__ src, float* __restrict__ dst, int ldb, int trans)
{
    size_t idx = (size_t)blockIdx.x * 256 + threadIdx.x;
    int lane = (int)(idx & 31);
    int nt   = (int)((idx >> 5) & 15);
    int c8   = (int)((idx >> 9) & 127);
    int nblk = (int)(idx >> 16);
    int n = nblk * 128 + nt * 8 + (lane >> 2);
    int k = c8 * 8 + (lane & 3);
    float2 v;
    if (trans) {
        v.x = f2tf32(src[(size_t)k * ldb + n]);
        v.y = f2tf32(src[(size_t)(k + 4) * ldb + n]);
    } else {
        v.x = f2tf32(src[(size_t)n * ldb + k]);
        v.y = f2tf32(src[(size_t)n * ldb + k + 4]);
    }
    ((float2*)dst)[idx] = v;
}

// ---------------- f16 gate weight fragment pack ----------------
// uint4 idx: [blk:128][cc:16][c16:8][mt:2][lane:32]; A-frag halves:
// (m,k0),(m,k0+1) | (m+8,k0),(m+8,k0+1) | (m,k0+8),(m,k0+9) | (m+8,k0+8),(m+8,k0+9)
__global__ __launch_bounds__(256) void k_packWFH(
    const float* __restrict__ W_ih, const float* __restrict__ W_hh)
{
    int idx = blockIdx.x * 256 + threadIdx.x;      // 0..1048575
    int lane = idx & 31;
    int mt   = (idx >> 5) & 1;
    int c16  = (idx >> 6) & 7;
    int cc   = (idx >> 9) & 15;
    int blk  = idx >> 13;
    int grp = lane >> 2, tg = lane & 3;
    int m = mt * 16 + grp;
    int kbase = cc * 128 + c16 * 16 + tg * 2;

    auto wval = [&](int mm, int kk) -> float {
        int g = mm >> 3, jo = mm & 7;
        int r = g * 1024 + blk * 8 + jo;
        return (kk < 1024) ? W_ih[(size_t)r * 2048 + 1024 + kk]
                           : W_hh[(size_t)r * 1024 + (kk - 1024)];
    };
    __half2 h0 = __floats2half2_rn(wval(m,     kbase),     wval(m,     kbase + 1));
    __half2 h1 = __floats2half2_rn(wval(m + 8, kbase),     wval(m + 8, kbase + 1));
    __half2 h2 = __floats2half2_rn(wval(m,     kbase + 8), wval(m,     kbase + 9));
    __half2 h3 = __floats2half2_rn(wval(m + 8, kbase + 8), wval(m + 8, kbase + 9));
    uint4 v;
    v.x = *(uint32_t*)&h0; v.y = *(uint32_t*)&h1;
    v.z = *(uint32_t*)&h2; v.w = *(uint32_t*)&h3;
    ((uint4*)g_Wfh)[idx] = v;
}

// ---------------- W_out f16 B-fragment pack (unchanged from R15) ----------------
__global__ __launch_bounds__(256) void k_packWoH(const float* __restrict__ W_out)
{
    size_t idx = (size_t)blockIdx.x * 256 + threadIdx.x;
    int lane  = (int)(idx & 31);
    int ntile = (int)((idx >> 5) & 15);
    int c16   = (int)((idx >> 9) & 63);
    int nblk  = (int)(idx >> 15);
    int grp = lane >> 2, tg = lane & 3;
    int n = nblk * 128 + ntile * 8 + grp;
    int k = c16 * 16 + tg * 2;
    const float* src = W_out + (size_t)n * HH + k;
    __half2 lo = __floats2half2_rn(src[0], src[1]);
    __half2 hi = __floats2half2_rn(src[8], src[9]);
    ((__half2*)g_Wo)[idx * 2]     = lo;
    ((__half2*)g_Wo)[idx * 2 + 1] = hi;
}

// ---------------- no-CCTL global barrier ----------------
__device__ __forceinline__ void gridbar(unsigned target) {
    __syncthreads();
    if (threadIdx.x == 0) {
        unsigned one = 1u, x;
        asm volatile("red.release.gpu.global.add.u32 [%0], %1;"
                     :: "l"(&g_bar), "r"(one) : "memory");
        do {
            asm volatile("ld.acquire.gpu.global.u32 %0, [%1];"
                         : "=r"(x) : "l"(&g_bar));
        } while (x < target);
    }
    __syncthreads();
}

// ---------------- persistent recurrence (P3 now f16) ----------------
__global__ __launch_bounds__(1024, 1) void k_recur(
    const float* __restrict__ memory,
    const float* __restrict__ b_ih, const float* __restrict__ b_hh)
{
    extern __shared__ char smem[];
    float* gate_s = (float*)(smem + OFF_GATE);
    float* p2s    = (float*)(smem + OFF_P2S);
    const uint32_t sbase = smem_u32(smem);
    const uint32_t mb0 = sbase, mb1 = sbase + 8;

    const int tid = threadIdx.x, bid = blockIdx.x;
    const int w = tid >> 5, lane = tid & 31;
    const bool gateblk = (bid < 128);

    if (tid == 0) {
        asm volatile("mbarrier.init.shared.b64 [%0], %1;" :: "r"(mb0), "r"(1u) : "memory");
        asm volatile("mbarrier.init.shared.b64 [%0], %1;" :: "r"(mb1), "r"(1u) : "memory");
    }
    __syncthreads();

    unsigned tgt = NB;

    for (int t = 0; t < TT; t++) {
        const int par = t & 1;

        auto issue = [&](int cc, int slot) {
            uint32_t mb = (slot & 1) ? mb1 : mb0;
            uint32_t wd = sbase + OFF_W + (slot & 1) * 8192;
            uint32_t xd = sbase + OFF_X + (slot & 1) * 8192;
            const __half* ws = g_Wfh + ((size_t)bid * 16 + cc) * 4096;
            int ccp = (cc < 8) ? cc : (cc + par * 8);
            const __half* xs = g_xfh + (size_t)ccp * 4096;
            asm volatile("mbarrier.arrive.expect_tx.shared.b64 _, [%0], %1;"
                         :: "r"(mb), "r"(16384u) : "memory");
            BULK_CPN(wd, ws, 8192u, mb);
            BULK_CPN(xd, xs, 8192u, mb);
        };

        if (gateblk && tid == 0) { issue(8, 0); issue(9, 1); }

        // ======== P1: scores ========
        for (int p = bid * 32 + w; p < BB * SS; p += NB * 32) {
            int b = p / SS;
            const float4* m4 = (const float4*)(g_M2 + (size_t)p * HH);
            const float4* h4 = (const float4*)(g_h + b * HH);
            float a = 0.f;
            #pragma unroll
            for (int i = 0; i < 8; i++) {
                float4 mv = m4[i * 32 + lane];
                float4 hv = __ldcg(&h4[i * 32 + lane]);
                a += mv.x*hv.x + mv.y*hv.y + mv.z*hv.z + mv.w*hv.w;
            }
            #pragma unroll
            for (int o = 16; o; o >>= 1) a += __shfl_xor_sync(0xffffffffu, a, o);
            if (!lane) g_scores[p] = a;
        }
        gridbar(tgt); tgt += NB;

        // ======== P2: softmax + ctx -> f16 x fragments ========
        if (gateblk) {
            float* red  = p2s;
            float* swp  = p2s + 256;
            float* part = p2s + 512;
            int b = bid >> 2, jblk = bid & 3;
            float v = -1e30f;
            if (tid < 256) {
                v = (tid < SS) ? __ldcg(&g_scores[b * SS + tid]) : -1e30f;
                red[tid] = v;
            }
            __syncthreads();
            for (int o = 128; o; o >>= 1) { if (tid < o) red[tid] = fmaxf(red[tid], red[tid+o]); __syncthreads(); }
            float mx = red[0]; __syncthreads();
            float e = 0.f;
            if (tid < 256) { e = (tid < SS) ? expf(v - mx) : 0.f; red[tid] = e; }
            __syncthreads();
            for (int o = 128; o; o >>= 1) { if (tid < o) red[tid] += red[tid+o]; __syncthreads(); }
            float inv = 1.f / red[0];
            if (tid < 256) swp[tid] = e * inv;
            __syncthreads();

            int jj = tid & 255, sp = tid >> 8;
            int j = jblk * 256 + jj;
            const float* mp = memory + ((size_t)b * SS + sp * 49) * HH + j;
            float acc2 = 0.f;
            #pragma unroll 7
            for (int s = 0; s < 49; s++)
                acc2 += swp[sp * 49 + s] * mp[(size_t)s * HH];
            part[sp * 256 + jj] = acc2;
            __syncthreads();
            if (tid < 256) {
                float cv = part[jj] + part[256+jj] + part[512+jj] + part[768+jj];
                g_xfh[xf_off_h(j, b, 0)] = __float2half_rn(cv);
            }
            __syncthreads();
            if (tid == 0) {
                unsigned one = 1u;
                asm volatile("red.release.gpu.global.add.u32 [%0], %1;"
                             :: "l"(&g_p2done), "r"(one) : "memory");
            }
        }

        // ======== P3: f16 gates pipeline (h-first) + cell ========
        if (gateblk) {
            if (tid < 256) {
                const int w8 = tid >> 5;
                const int mt = w8 & 1, nt = w8 >> 1;
                const int grp = lane >> 2, tg = lane & 3;
                float acc[4] = {0.f, 0.f, 0.f, 0.f};

                #pragma unroll
                for (int i = 0; i < 16; i++) {
                    uint32_t mb = (i & 1) ? mb1 : mb0;
                    MB_WAIT(mb, (i >> 1) & 1);
                    const uint4* wb = (const uint4*)(smem + OFF_W + (i & 1) * 8192);
                    const uint2* xb = (const uint2*)(smem + OFF_X + (i & 1) * 8192);
                    #pragma unroll
                    for (int c16 = 0; c16 < 8; c16++) {
                        uint4 a4 = wb[(c16 * 2 + mt) * 32 + lane];
                        uint2 b2 = xb[(c16 * 4 + nt) * 32 + lane];
                        mma_f16(acc, a4, b2);
                    }
                    asm volatile("bar.sync 7, 256;" ::: "memory");
                    if (tid == 0 && i < 14) {
                        int nxt = (i + 2 + 8) & 15;
                        if (i == 6) {
                            unsigned x, want = 128u * (unsigned)(t + 1);
                            do {
                                asm volatile("ld.acquire.gpu.global.u32 %0, [%1];"
                                             : "=r"(x) : "l"(&g_p2done));
                            } while (x < want);
                        }
                        issue(nxt, i + 2);
                    }
                }

                *(float2*)&gate_s[(mt*16 + grp    ) * 32 + nt*8 + tg*2] = make_float2(acc[0], acc[1]);
                *(float2*)&gate_s[(mt*16 + grp + 8) * 32 + nt*8 + tg*2] = make_float2(acc[2], acc[3]);
            }
            __syncthreads();
            if (tid < 256) {
                int b = tid & 31, jo = tid >> 5;
                int j = bid * 8 + jo;
                float pre[4];
                #pragma unroll
                for (int g = 0; g < 4; g++) {
                    pre[g] = gate_s[(g*8 + jo) * 32 + b]
                           + __ldg(&g_ET[((size_t)t * RR + g*1024 + j) * 32 + b])
                           + __ldg(&b_ih[g*1024 + j]) + __ldg(&b_hh[g*1024 + j]);
                }
                float ig = 1.f / (1.f + expf(-pre[0]));
                float fg = 1.f / (1.f + expf(-pre[1]));
                float gg = tanhf(pre[2]);
                float og = 1.f / (1.f + expf(-pre[3]));
                int idx = b * HH + j;
                float cn = fg * g_c[idx] + ig * gg;
                float hn = og * tanhf(cn);
                g_c[idx] = cn;
                g_h[idx] = hn;
                g_xfh[xf_off_h(1024 + j, b, (t + 1) & 1)] = __float2half_rn(hn);
                // f16 A-fragment store for logits (m16n8k16 layout; proven R15)
                int m = t * 32 + b;
                int mblk = m >> 7, c16 = j >> 4, mtile = (m >> 4) & 7;
                int q   = ((m >> 3) & 1) + 2 * ((j >> 3) & 1);
                int lnA = ((m & 7) << 2) | ((j >> 1) & 3);
                size_t off = (((((size_t)mblk * 64 + c16) * 8 + mtile) * 32 + lnA) * 8)
                           + (size_t)(q * 2 + (j & 1));
                g_Af[off] = __float2half_rn(hn);
            }
        }
        gridbar(tgt); tgt += NB;
    }
}

// ---------------- f16 pipelined logits GEMM (unchanged from R15) ----------------
__global__ __launch_bounds__(256, 2) void k_logits(
    const float* __restrict__ bias, float* __restrict__ out)
{
    extern __shared__ char smem[];
    const uint32_t sbase = smem_u32(smem);
    const int tid = threadIdx.x;
    const int mblk = blockIdx.x, nblk = blockIdx.y;
    const int warp = tid >> 5, lane = tid & 31;
    const int wm = warp >> 1, wn = warp & 1;
    const int grp = lane >> 2, tg = lane & 3;

    if (tid == 0) {
        #pragma unroll
        for (int i = 0; i < 3; i++)
            asm volatile("mbarrier.init.shared.b64 [%0], %1;"
                         :: "r"(sbase + i * 8), "r"(1u) : "memory");
    }
    __syncthreads();

    float acc[2][8][4] = {};

    auto issue = [&](int s) {
        int buf = s % 3;
        uint32_t mb = sbase + buf * 8;
        uint32_t ad = sbase + 128 + buf * 16384;
        uint32_t bd = ad + 8192;
        const __half* as = g_Af + ((size_t)mblk * 64 + s * 2) * 2048;
        const __half* bs = g_Wo + ((size_t)nblk * 64 + s * 2) * 2048;
        asm volatile("mbarrier.arrive.expect_tx.shared.b64 _, [%0], %1;"
                     :: "r"(mb), "r"(16384u) : "memory");
        BULK_CPN(ad, as, 8192u, mb);
        BULK_CPN(bd, bs, 8192u, mb);
    };

    if (tid == 0) { issue(0); issue(1); }

    for (int s = 0; s < 32; s++) {
        int buf = s % 3;
        MB_WAIT(sbase + buf * 8, (s / 3) & 1);
        const uint4* Ab = (const uint4*)(smem + 128 + buf * 16384);
        const uint2* Bb = (const uint2*)(smem + 128 + buf * 16384 + 8192);
        #pragma unroll
        for (int cl = 0; cl < 2; cl++) {
            uint4 a0 = Ab[(cl * 8 + wm * 2 + 0) * 32 + lane];
            uint4 a1 = Ab[(cl * 8 + wm * 2 + 1) * 32 + lane];
            #pragma unroll
            for (int nt = 0; nt < 8; nt++) {
                uint2 b2 = Bb[(cl * 16 + wn * 8 + nt) * 32 + lane];
                mma_f16(acc[0][nt], a0, b2);
                mma_f16(acc[1][nt], a1, b2);
            }
        }
        __syncthreads();
        if (tid == 0 && s + 2 < 32) issue(s + 2);
    }

    #pragma unroll
    for (int mt = 0; mt < 2; mt++) {
        int m0 = mblk * 128 + (wm * 2 + mt) * 16 + grp;
        int m2 = m0 + 8;
        #pragma unroll
        for (int nt = 0; nt < 8; nt++) {
            int ng = nblk * 128 + wn * 64 + nt * 8 + tg * 2;
            float* a4 = acc[mt][nt];
            float b0 = __ldg(bias + ng), b1 = __ldg(bias + ng + 1);
            size_t r1 = ((size_t)(m0 & 31) * TT + (m0 >> 5)) * VV;
            size_t r2 = ((size_t)(m2 & 31) * TT + (m2 >> 5)) * VV;
            *(float2*)(out + r1 + ng) = make_float2(a4[0] + b0, a4[1] + b1);
            *(float2*)(out + r2 + ng) = make_float2(a4[2] + b0, a4[3] + b1);
        }
    }
}

// ---------------- tf32 pipelined GEMM (prologue M2 / E; unchanged) ----------------
__global__ __launch_bounds__(256, 2) void k_pgemm(
    const float* __restrict__ Afrag, const float* __restrict__ Bfrag,
    float* __restrict__ C, int Nn, int mode)
{
    extern __shared__ char smem[];
    const uint32_t sbase = smem_u32(smem);
    const int tid = threadIdx.x;
    const int mblk = blockIdx.x, nblk = blockIdx.y;
    const int warp = tid >> 5, lane = tid & 31;
    const int wm = warp >> 1, wn = warp & 1;
    const int grp = lane >> 2, tg = lane & 3;

    if (tid == 0) {
        #pragma unroll
        for (int i = 0; i < 3; i++)
            asm volatile("mbarrier.init.shared.b64 [%0], %1;"
                         :: "r"(sbase + i * 8), "r"(1u) : "memory");
    }
    __syncthreads();

    float acc[2][8][4] = {};

    auto issue = [&](int s) {
        int buf = s % 3;
        uint32_t mb = sbase + buf * 8;
        uint32_t ad = sbase + 128 + buf * 32768;
        uint32_t bd = ad + 16384;
        const float* as = Afrag + ((size_t)mblk * 128 + s * 4) * 1024;
        const float* bs = Bfrag + ((size_t)nblk * 128 + s * 4) * 1024;
        asm volatile("mbarrier.arrive.expect_tx.shared.b64 _, [%0], %1;"
                     :: "r"(mb), "r"(32768u) : "memory");
        BULK_CPN(ad, as, 16384u, mb);
        BULK_CPN(bd, bs, 16384u, mb);
    };

    if (tid == 0) { issue(0); issue(1); }

    for (int s = 0; s < 32; s++) {
        int buf = s % 3;
        MB_WAIT(sbase + buf * 8, (s / 3) & 1);
        const float4* Ab = (const float4*)(smem + 128 + buf * 32768);
        const float2* Bb = (const float2*)(smem + 128 + buf * 32768 + 16384);
        #pragma unroll
        for (int c8 = 0; c8 < 4; c8++) {
            float4 a0 = Ab[(c8 * 8 + wm * 2 + 0) * 32 + lane];
            float4 a1 = Ab[(c8 * 8 + wm * 2 + 1) * 32 + lane];
            #pragma unroll
            for (int nt = 0; nt < 8; nt++) {
                float2 b2 = Bb[(c8 * 16 + wn * 8 + nt) * 32 + lane];
                mma_op(acc[0][nt], (const uint32_t*)&a0, (const uint32_t*)&b2);
                mma_op(acc[1][nt], (const uint32_t*)&a1, (const uint32_t*)&b2);
            }
        }
        __syncthreads();
        if (tid == 0 && s + 2 < 32) issue(s + 2);
    }

    #pragma unroll
    for (int mt = 0; mt < 2; mt++) {
        int m0 = mblk * 128 + (wm * 2 + mt) * 16 + grp;
        int m2 = m0 + 8;
        #pragma unroll
        for (int nt = 0; nt < 8; nt++) {
            int ng = nblk * 128 + wn * 64 + nt * 8 + tg * 2;
            float* a4 = acc[mt][nt];
            if (mode == 2) {
                int b1i = m0 >> 6, t1 = m0 & 63;
                int b2i = m2 >> 6, t2 = m2 & 63;
                size_t p1 = ((size_t)t1 * RR + ng) * 32 + b1i;
                size_t p2 = ((size_t)t2 * RR + ng) * 32 + b2i;
                C[p1] = a4[0]; C[p1 + 32] = a4[1];
                C[p2] = a4[2]; C[p2 + 32] = a4[3];
            } else {
                *(float2*)(C + (size_t)m0 * Nn + ng) = make_float2(a4[0], a4[1]);
                *(float2*)(C + (size_t)m2 * Nn + ng) = make_float2(a4[2], a4[3]);
            }
        }
    }
}

// ---------------- small kernels ----------------
__global__ void k_zero() {
    int i = blockIdx.x * 1024 + threadIdx.x;     // 32768 threads
    g_h[i] = 0.f; g_c[i] = 0.f;
    uint32_t* xw = (uint32_t*)g_xfh;             // 49152 words
    for (int j = i; j < 49152; j += 32768) xw[j] = 0u;
    if (i == 0) { g_bar = 0u; g_p2done = 0u; }
}

__global__ void k_copy_hc(float* __restrict__ out) {
    int i = blockIdx.x * 512 + threadIdx.x;
    const size_t OFF = (size_t)BB * TT * VV;
    out[OFF + i] = g_h[i];
    out[OFF + (size_t)BB*HH + i] = g_c[i];
}

// ---------------- launch ----------------
extern "C" void kernel_launch(void* const* d_in, const int* in_sizes, int n_in,
                              void* d_out, int out_size)
{
    const float* memory  = (const float*)d_in[0];
    const int*   captions= (const int*  )d_in[1];
    const float* emb     = (const float*)d_in[2];
    const float* attn_W  = (const float*)d_in[3];
    const float* W_ih    = (const float*)d_in[4];
    const float* W_hh    = (const float*)d_in[5];
    const float* b_ih    = (const float*)d_in[6];
    const float* b_hh    = (const float*)d_in[7];
    const float* W_out   = (const float*)d_in[8];
    const float* b_out   = (const float*)d_in[9];
    float* out = (float*)d_out;

    static float *pM2 = nullptr, *pET = nullptr,
                 *pAM2 = nullptr, *pBM2 = nullptr, *pAE = nullptr, *pBE = nullptr;
    if (!pM2) {
        cudaGetSymbolAddress((void**)&pM2,  g_M2);
        cudaGetSymbolAddress((void**)&pET,  g_ET);
        cudaGetSymbolAddress((void**)&pAM2, g_AM2);
        cudaGetSymbolAddress((void**)&pBM2, g_BM2);
        cudaGetSymbolAddress((void**)&pAE,  g_AE);
        cudaGetSymbolAddress((void**)&pBE,  g_BE);
        cudaFuncSetAttribute(k_recur,  cudaFuncAttributeMaxDynamicSharedMemorySize, SMEM_RECUR);
        cudaFuncSetAttribute(k_pgemm,  cudaFuncAttributeMaxDynamicSharedMemorySize, SMEM_WK);
        cudaFuncSetAttribute(k_logits, cudaFuncAttributeMaxDynamicSharedMemorySize, SMEM_LF);
    }

    k_zero<<<32, 1024>>>();

    // fragment packs
    k_packA<<<6272, 256>>>(memory, nullptr, nullptr, pAM2);
    k_packB<<<2048, 256>>>(attn_W, pBM2, HH, 1);
    k_packA<<<2048, 256>>>(nullptr, captions, emb, pAE);
    k_packB<<<8192, 256>>>(W_ih, pBE, 2048, 0);
    k_packWFH<<<4096, 256>>>(W_ih, W_hh);
    k_packWoH<<<32000, 256>>>(W_out);

    // prologue GEMMs
    k_pgemm<<<dim3(49, 8), 256, SMEM_WK>>>(pAM2, pBM2, pM2, HH, 0);
    k_pgemm<<<dim3(16, 32), 256, SMEM_WK>>>(pAE, pBE, pET, RR, 2);

    // recurrence (f16 gate pipeline)
    k_recur<<<NB, 1024, SMEM_RECUR>>>(memory, b_ih, b_hh);

    // f16 logits
    k_logits<<<dim3(16, 250), 256, SMEM_LF>>>(b_out, out);

    k_copy_hc<<<64, 512>>>(out);
}